// round 1
// baseline (speedup 1.0000x reference)
#include <cuda_runtime.h>
#include <cuda_bf16.h>
#include <math.h>

// Problem constants
#define Bb 2
#define Nn 2048
#define Hh 1024
#define NH 16
#define HD 64
#define SCALE 0.125f   // 64^-0.5

#define M_TOT (Bb*Nn)          // 4096

// Scratch (device globals; no allocations allowed)
__device__ float g_Q[Bb*NH*Nn*HD];      // [b,h,n,d]
__device__ float g_K[Bb*NH*Nn*HD];
__device__ float g_V[Bb*NH*Nn*HD];
__device__ float g_attn[M_TOT*Hh];      // [b*n, h*d]

// ---------------------------------------------------------------------------
// QKV projection: 64x64 output tile, K-tile 16, 256 threads, 4x4 microtile.
// z=0: Q = x  @ Wqkv[:,    0:1024]
// z=1: K = x2 @ Wqkv[:, 1024:2048]
// z=2: V = x2 @ Wqkv[:, 2048:3072]
// Output written head-major [b,h,n,d].
// ---------------------------------------------------------------------------
__global__ __launch_bounds__(256) void qkv_kernel(const float* __restrict__ x,
                                                  const float* __restrict__ x2,
                                                  const float* __restrict__ Wqkv)
{
    const int z  = blockIdx.z;
    const int c0 = blockIdx.x * 64;   // column within 1024 (one head per block: c0 = h*64)
    const int m0 = blockIdx.y * 64;   // row within 4096

    const float* A = (z == 0) ? x : x2;
    const float* Wbase = Wqkv + (size_t)z * 1024 + c0;

    __shared__ float As[16][68];   // transposed A tile: As[k][m]
    __shared__ float Ws[16][64];   // Ws[k][c]

    const int tx = threadIdx.x, ty = threadIdx.y;
    const int tid = ty * 16 + tx;

    float acc[4][4];
#pragma unroll
    for (int i = 0; i < 4; i++)
#pragma unroll
        for (int j = 0; j < 4; j++) acc[i][j] = 0.f;

    for (int k0 = 0; k0 < 1024; k0 += 16) {
        __syncthreads();
        // Load A tile [64 rows][16 k] : 1024 elems = 256 float4
        {
            int r  = tid / 4;
            int kq = (tid % 4) * 4;
            float4 v = *(const float4*)(A + (size_t)(m0 + r) * 1024 + k0 + kq);
            As[kq + 0][r] = v.x;
            As[kq + 1][r] = v.y;
            As[kq + 2][r] = v.z;
            As[kq + 3][r] = v.w;
        }
        // Load W tile [16 k][64 c]
        {
            int kk = tid / 16;
            int cc = (tid % 16) * 4;
            *(float4*)&Ws[kk][cc] =
                *(const float4*)(Wbase + (size_t)(k0 + kk) * 3072 + cc);
        }
        __syncthreads();
#pragma unroll
        for (int k = 0; k < 16; k++) {
            float4 a = *(float4*)&As[k][ty * 4];
            float4 w = *(float4*)&Ws[k][tx * 4];
            acc[0][0] += a.x * w.x; acc[0][1] += a.x * w.y; acc[0][2] += a.x * w.z; acc[0][3] += a.x * w.w;
            acc[1][0] += a.y * w.x; acc[1][1] += a.y * w.y; acc[1][2] += a.y * w.z; acc[1][3] += a.y * w.w;
            acc[2][0] += a.z * w.x; acc[2][1] += a.z * w.y; acc[2][2] += a.z * w.z; acc[2][3] += a.z * w.w;
            acc[3][0] += a.w * w.x; acc[3][1] += a.w * w.y; acc[3][2] += a.w * w.z; acc[3][3] += a.w * w.w;
        }
    }

    // Epilogue: head-major [b,h,n,d]
    float* dst = (z == 0) ? g_Q : (z == 1) ? g_K : g_V;
    const int b = m0 / Nn;
    const int h = c0 / HD;                // block covers exactly one head
#pragma unroll
    for (int i = 0; i < 4; i++) {
        int n  = (m0 % Nn) + ty * 4 + i;
        int dd = tx * 4;
        size_t idx = ((((size_t)b * NH + h) * Nn) + n) * HD + dd;
        float4 o = make_float4(acc[i][0], acc[i][1], acc[i][2], acc[i][3]);
        *(float4*)(dst + idx) = o;
    }
}

// ---------------------------------------------------------------------------
// Flash attention: one block = 64 queries of one (b,h). KV tiles of 64.
// blockDim (16,16); each thread owns a 4x4 S/P microtile and 4x4 O microtile.
// smem: Qs[64][68], KsT[64][68] (d-major), Vs[64][68], Ps[64][68]
// ---------------------------------------------------------------------------
#define ASTRIDE 68
__global__ __launch_bounds__(256) void attn_kernel()
{
    const int bh = blockIdx.y;            // 0..31
    const int q0 = blockIdx.x * 64;

    const float* Q = g_Q + (size_t)bh * Nn * HD;
    const float* K = g_K + (size_t)bh * Nn * HD;
    const float* V = g_V + (size_t)bh * Nn * HD;

    extern __shared__ float sm[];
    float* Qs  = sm;                       // [64][68]  (row, d)
    float* KsT = Qs  + 64 * ASTRIDE;       // [64][68]  (d, row)  -- transposed
    float* Vs  = KsT + 64 * ASTRIDE;       // [64][68]  (row, d)
    float* Ps  = Vs  + 64 * ASTRIDE;       // [64][68]

    const int tx = threadIdx.x, ty = threadIdx.y;
    const int tid = ty * 16 + tx;

    // Load Q tile
    for (int e = tid; e < 64 * 16; e += 256) {
        int r  = e / 16;
        int c4 = (e % 16) * 4;
        *(float4*)(Qs + r * ASTRIDE + c4) =
            *(const float4*)(Q + (size_t)(q0 + r) * HD + c4);
    }

    float m_i[4], l_i[4], O[4][4];
#pragma unroll
    for (int i = 0; i < 4; i++) {
        m_i[i] = -INFINITY; l_i[i] = 0.f;
#pragma unroll
        for (int j = 0; j < 4; j++) O[i][j] = 0.f;
    }

    for (int t = 0; t < Nn / 64; ++t) {
        __syncthreads();  // protect prior Ps/KsT/Vs consumers
        // Load K (transposed) and V tiles
        for (int e = tid; e < 64 * 16; e += 256) {
            int r  = e / 16;
            int c4 = (e % 16) * 4;
            float4 kv = *(const float4*)(K + (size_t)(t * 64 + r) * HD + c4);
            KsT[(c4 + 0) * ASTRIDE + r] = kv.x;
            KsT[(c4 + 1) * ASTRIDE + r] = kv.y;
            KsT[(c4 + 2) * ASTRIDE + r] = kv.z;
            KsT[(c4 + 3) * ASTRIDE + r] = kv.w;
            *(float4*)(Vs + r * ASTRIDE + c4) =
                *(const float4*)(V + (size_t)(t * 64 + r) * HD + c4);
        }
        __syncthreads();

        // S = Q * K^T  (4x4 microtile)
        float S[4][4];
#pragma unroll
        for (int i = 0; i < 4; i++)
#pragma unroll
            for (int j = 0; j < 4; j++) S[i][j] = 0.f;

#pragma unroll 8
        for (int k = 0; k < 64; k++) {
            float q0f = Qs[(ty * 4 + 0) * ASTRIDE + k];
            float q1f = Qs[(ty * 4 + 1) * ASTRIDE + k];
            float q2f = Qs[(ty * 4 + 2) * ASTRIDE + k];
            float q3f = Qs[(ty * 4 + 3) * ASTRIDE + k];
            float4 kf = *(float4*)(KsT + k * ASTRIDE + tx * 4);
            S[0][0] += q0f * kf.x; S[0][1] += q0f * kf.y; S[0][2] += q0f * kf.z; S[0][3] += q0f * kf.w;
            S[1][0] += q1f * kf.x; S[1][1] += q1f * kf.y; S[1][2] += q1f * kf.z; S[1][3] += q1f * kf.w;
            S[2][0] += q2f * kf.x; S[2][1] += q2f * kf.y; S[2][2] += q2f * kf.z; S[2][3] += q2f * kf.w;
            S[3][0] += q3f * kf.x; S[3][1] += q3f * kf.y; S[3][2] += q3f * kf.z; S[3][3] += q3f * kf.w;
        }

        // Online softmax update per row (replicated across the 16 tx lanes)
#pragma unroll
        for (int i = 0; i < 4; i++) {
            float s0 = S[i][0] * SCALE, s1 = S[i][1] * SCALE,
                  s2 = S[i][2] * SCALE, s3 = S[i][3] * SCALE;
            float rm = fmaxf(fmaxf(s0, s1), fmaxf(s2, s3));
#pragma unroll
            for (int off = 8; off >= 1; off >>= 1)
                rm = fmaxf(rm, __shfl_xor_sync(0xffffffffu, rm, off));
            float mn = fmaxf(m_i[i], rm);
            float alpha = __expf(m_i[i] - mn);
            m_i[i] = mn;
            float p0 = __expf(s0 - mn);
            float p1 = __expf(s1 - mn);
            float p2 = __expf(s2 - mn);
            float p3 = __expf(s3 - mn);
            float rs = p0 + p1 + p2 + p3;
#pragma unroll
            for (int off = 8; off >= 1; off >>= 1)
                rs += __shfl_xor_sync(0xffffffffu, rs, off);
            l_i[i] = l_i[i] * alpha + rs;
#pragma unroll
            for (int j = 0; j < 4; j++) O[i][j] *= alpha;
            *(float4*)(Ps + (ty * 4 + i) * ASTRIDE + tx * 4) =
                make_float4(p0, p1, p2, p3);
        }
        __syncthreads();

        // O += P * V
#pragma unroll 8
        for (int c = 0; c < 64; c++) {
            float p0f = Ps[(ty * 4 + 0) * ASTRIDE + c];
            float p1f = Ps[(ty * 4 + 1) * ASTRIDE + c];
            float p2f = Ps[(ty * 4 + 2) * ASTRIDE + c];
            float p3f = Ps[(ty * 4 + 3) * ASTRIDE + c];
            float4 vf = *(float4*)(Vs + c * ASTRIDE + tx * 4);
            O[0][0] += p0f * vf.x; O[0][1] += p0f * vf.y; O[0][2] += p0f * vf.z; O[0][3] += p0f * vf.w;
            O[1][0] += p1f * vf.x; O[1][1] += p1f * vf.y; O[1][2] += p1f * vf.z; O[1][3] += p1f * vf.w;
            O[2][0] += p2f * vf.x; O[2][1] += p2f * vf.y; O[2][2] += p2f * vf.z; O[2][3] += p2f * vf.w;
            O[3][0] += p3f * vf.x; O[3][1] += p3f * vf.y; O[3][2] += p3f * vf.z; O[3][3] += p3f * vf.w;
        }
    }

    // Normalize and write to g_attn: [b*n, h*64 + d]
    const int b = bh / NH;
    const int h = bh % NH;
#pragma unroll
    for (int i = 0; i < 4; i++) {
        float inv = 1.f / l_i[i];
        size_t row = (size_t)b * Nn + q0 + ty * 4 + i;
        float4 o = make_float4(O[i][0] * inv, O[i][1] * inv,
                               O[i][2] * inv, O[i][3] * inv);
        *(float4*)(g_attn + row * Hh + h * HD + tx * 4) = o;
    }
}

// ---------------------------------------------------------------------------
// Output projection: out = g_attn @ Wout + bout   ([4096,1024]@[1024,1024])
// ---------------------------------------------------------------------------
__global__ __launch_bounds__(256) void proj_kernel(const float* __restrict__ Wout,
                                                   const float* __restrict__ bout,
                                                   float* __restrict__ out)
{
    const int c0 = blockIdx.x * 64;
    const int m0 = blockIdx.y * 64;

    __shared__ float As[16][68];
    __shared__ float Ws[16][64];

    const int tx = threadIdx.x, ty = threadIdx.y;
    const int tid = ty * 16 + tx;

    float acc[4][4];
#pragma unroll
    for (int i = 0; i < 4; i++)
#pragma unroll
        for (int j = 0; j < 4; j++) acc[i][j] = 0.f;

    for (int k0 = 0; k0 < 1024; k0 += 16) {
        __syncthreads();
        {
            int r  = tid / 4;
            int kq = (tid % 4) * 4;
            float4 v = *(const float4*)(g_attn + (size_t)(m0 + r) * 1024 + k0 + kq);
            As[kq + 0][r] = v.x;
            As[kq + 1][r] = v.y;
            As[kq + 2][r] = v.z;
            As[kq + 3][r] = v.w;
        }
        {
            int kk = tid / 16;
            int cc = (tid % 16) * 4;
            *(float4*)&Ws[kk][cc] =
                *(const float4*)(Wout + (size_t)(k0 + kk) * 1024 + c0 + cc);
        }
        __syncthreads();
#pragma unroll
        for (int k = 0; k < 16; k++) {
            float4 a = *(float4*)&As[k][ty * 4];
            float4 w = *(float4*)&Ws[k][tx * 4];
            acc[0][0] += a.x * w.x; acc[0][1] += a.x * w.y; acc[0][2] += a.x * w.z; acc[0][3] += a.x * w.w;
            acc[1][0] += a.y * w.x; acc[1][1] += a.y * w.y; acc[1][2] += a.y * w.z; acc[1][3] += a.y * w.w;
            acc[2][0] += a.z * w.x; acc[2][1] += a.z * w.y; acc[2][2] += a.z * w.z; acc[2][3] += a.z * w.w;
            acc[3][0] += a.w * w.x; acc[3][1] += a.w * w.y; acc[3][2] += a.w * w.z; acc[3][3] += a.w * w.w;
        }
    }

    float4 bb = *(const float4*)(bout + c0 + tx * 4);
#pragma unroll
    for (int i = 0; i < 4; i++) {
        size_t row = (size_t)m0 + ty * 4 + i;
        float4 o = make_float4(acc[i][0] + bb.x, acc[i][1] + bb.y,
                               acc[i][2] + bb.z, acc[i][3] + bb.w);
        *(float4*)(out + row * 1024 + c0 + tx * 4) = o;
    }
}

// ---------------------------------------------------------------------------
extern "C" void kernel_launch(void* const* d_in, const int* in_sizes, int n_in,
                              void* d_out, int out_size)
{
    const float* x    = (const float*)d_in[0];
    const float* x2   = (const float*)d_in[1];
    const float* Wqkv = (const float*)d_in[2];
    const float* Wout = (const float*)d_in[3];
    const float* bout = (const float*)d_in[4];
    float* out = (float*)d_out;

    dim3 blk(16, 16);

    // 1) QKV projections
    qkv_kernel<<<dim3(16, 64, 3), blk>>>(x, x2, Wqkv);

    // 2) Flash attention
    const size_t attn_smem = 4 * 64 * ASTRIDE * sizeof(float);  // 69,632 B
    cudaFuncSetAttribute(attn_kernel,
                         cudaFuncAttributeMaxDynamicSharedMemorySize,
                         (int)attn_smem);
    attn_kernel<<<dim3(Nn / 64, Bb * NH), blk, attn_smem>>>();

    // 3) Output projection
    proj_kernel<<<dim3(16, 64), blk>>>(Wout, bout, out);
}

// round 3
// speedup vs baseline: 1.3362x; 1.3362x over previous
#include <cuda_runtime.h>
#include <cuda_bf16.h>
#include <math.h>
#include <stdint.h>

// Problem constants
#define Bb 2
#define Nn 2048
#define Hh 1024
#define NH 16
#define HD 64
#define SCALE 0.125f
#define Kdim 1024
#define M_TOT (Bb*Nn)   // 4096

// ---------------------------------------------------------------------------
// Scratch (device globals; no allocations allowed)
// ---------------------------------------------------------------------------
__device__ __align__(128) __nv_bfloat16 g_Xhi [M_TOT*Kdim];
__device__ __align__(128) __nv_bfloat16 g_Xlo [M_TOT*Kdim];
__device__ __align__(128) __nv_bfloat16 g_X2hi[M_TOT*Kdim];
__device__ __align__(128) __nv_bfloat16 g_X2lo[M_TOT*Kdim];
__device__ __align__(128) __nv_bfloat16 g_Wqhi[3*Hh*Kdim];   // Wqkv^T [3072][1024]
__device__ __align__(128) __nv_bfloat16 g_Wqlo[3*Hh*Kdim];
__device__ __align__(128) __nv_bfloat16 g_Wohi[Hh*Kdim];     // Wout^T [1024][1024]
__device__ __align__(128) __nv_bfloat16 g_Wolo[Hh*Kdim];
__device__ __align__(128) float g_Q[Bb*NH*Nn*HD];            // [b,h,n,d] fp32
__device__ __align__(128) float g_K[Bb*NH*Nn*HD];
__device__ __align__(128) float g_V[Bb*NH*Nn*HD];
__device__ __align__(128) __nv_bfloat16 g_Ahi[M_TOT*Hh];     // attn out split [b*n][h*d]
__device__ __align__(128) __nv_bfloat16 g_Alo[M_TOT*Hh];

// ---------------------------------------------------------------------------
// PTX helpers (portable: cp.async + ldmatrix + mma.sync — no tcgen05)
// ---------------------------------------------------------------------------
__device__ __forceinline__ uint32_t smem_u32(const void* p) {
    return (uint32_t)__cvta_generic_to_shared(p);
}
__device__ __forceinline__ void cp_async16(uint32_t d, const void* s) {
    asm volatile("cp.async.cg.shared.global [%0], [%1], 16;\n" :: "r"(d), "l"(s) : "memory");
}
__device__ __forceinline__ void cp_commit() { asm volatile("cp.async.commit_group;\n" ::: "memory"); }
__device__ __forceinline__ void cp_wait1()  { asm volatile("cp.async.wait_group 1;\n" ::: "memory"); }
__device__ __forceinline__ void ldsm_x4(uint32_t& r0, uint32_t& r1, uint32_t& r2, uint32_t& r3, uint32_t a) {
    asm volatile("ldmatrix.sync.aligned.m8n8.x4.shared.b16 {%0,%1,%2,%3}, [%4];"
                 : "=r"(r0), "=r"(r1), "=r"(r2), "=r"(r3) : "r"(a));
}
__device__ __forceinline__ void mma16816(float c[4], const uint32_t a[4], const uint32_t b[2]) {
    asm volatile("mma.sync.aligned.m16n8k16.row.col.f32.bf16.bf16.f32 "
                 "{%0,%1,%2,%3}, {%4,%5,%6,%7}, {%8,%9}, {%0,%1,%2,%3};"
                 : "+f"(c[0]), "+f"(c[1]), "+f"(c[2]), "+f"(c[3])
                 : "r"(a[0]), "r"(a[1]), "r"(a[2]), "r"(a[3]), "r"(b[0]), "r"(b[1]));
}

// ---------------------------------------------------------------------------
// GEMM tiling constants
// ---------------------------------------------------------------------------
#define BMt 128
#define BNt 128
#define KCc 32
#define PITCHB 80                   // bytes per smem row (32 bf16 + 8 pad)
#define TILE_BYTES (128*PITCHB)     // 10240
#define BUF_BYTES (4*TILE_BYTES)    // Ahi|Alo|Bhi|Blo = 40960
#define GEMM_SMEM (2*BUF_BYTES)     // double buffer = 81920

// ---------------------------------------------------------------------------
// Conversion: fp32 -> bf16 hi/lo split (element-wise)
// ---------------------------------------------------------------------------
__global__ __launch_bounds__(256) void split_kernel(const float* __restrict__ src,
                                                    __nv_bfloat16* __restrict__ hi,
                                                    __nv_bfloat16* __restrict__ lo,
                                                    int n4)
{
    int i = blockIdx.x * blockDim.x + threadIdx.x;
    if (i >= n4) return;
    float4 v = ((const float4*)src)[i];
    __nv_bfloat16 h0 = __float2bfloat16(v.x), h1 = __float2bfloat16(v.y),
                  h2 = __float2bfloat16(v.z), h3 = __float2bfloat16(v.w);
    __nv_bfloat16 l0 = __float2bfloat16(v.x - __bfloat162float(h0));
    __nv_bfloat16 l1 = __float2bfloat16(v.y - __bfloat162float(h1));
    __nv_bfloat16 l2 = __float2bfloat16(v.z - __bfloat162float(h2));
    __nv_bfloat16 l3 = __float2bfloat16(v.w - __bfloat162float(h3));
    __nv_bfloat162* H = (__nv_bfloat162*)(hi + (size_t)i * 4);
    H[0] = __halves2bfloat162(h0, h1); H[1] = __halves2bfloat162(h2, h3);
    __nv_bfloat162* L = (__nv_bfloat162*)(lo + (size_t)i * 4);
    L[0] = __halves2bfloat162(l0, l1); L[1] = __halves2bfloat162(l2, l3);
}

// Transpose + split: src [1024][C] fp32 -> dst [C][1024] bf16 hi/lo
__global__ __launch_bounds__(256) void tsplit_kernel(const float* __restrict__ src,
                                                     __nv_bfloat16* __restrict__ hi,
                                                     __nv_bfloat16* __restrict__ lo,
                                                     int C)
{
    __shared__ float tile[32][33];
    int c0 = blockIdx.x * 32, k0 = blockIdx.y * 32;
    int tx = threadIdx.x, ty = threadIdx.y;  // 32x8
#pragma unroll
    for (int i = 0; i < 32; i += 8)
        tile[ty + i][tx] = src[(size_t)(k0 + ty + i) * C + c0 + tx];
    __syncthreads();
#pragma unroll
    for (int i = 0; i < 32; i += 8) {
        float v = tile[tx][ty + i];
        __nv_bfloat16 h = __float2bfloat16(v);
        __nv_bfloat16 l = __float2bfloat16(v - __bfloat162float(h));
        size_t o = (size_t)(c0 + ty + i) * 1024 + k0 + tx;
        hi[o] = h; lo[o] = l;
    }
}

// ---------------------------------------------------------------------------
// HMMA GEMM mainloop: C[128,128] = (Ahi+Alo)@(Bhi+Blo)^T over K=1024
//   A*: [128 rows][1024] k-major   B*: [128 out-cols][1024] k-major
// 8 warps: warp tile 64x32 (wm = (wid>>2)*64, wn = (wid&3)*32)
// acc[mt][nt][4]: mt in 0..3 (16-row tiles), nt in 0..3 (8-col tiles)
// ---------------------------------------------------------------------------
__device__ __forceinline__ void load_chunk(const __nv_bfloat16* A0, const __nv_bfloat16* A1,
                                           const __nv_bfloat16* B0, const __nv_bfloat16* B1,
                                           uint32_t smbuf, int c, int tid)
{
    int row  = tid >> 1;
    int half = (tid & 1) * 2;        // 16B-segment base: 0 or 2
    size_t g = (size_t)row * Kdim + (size_t)c * KCc + half * 8;
    uint32_t s = smbuf + row * PITCHB + half * 16;
    cp_async16(s,                       A0 + g);
    cp_async16(s + 16,                  A0 + g + 8);
    cp_async16(s + TILE_BYTES,          A1 + g);
    cp_async16(s + TILE_BYTES + 16,     A1 + g + 8);
    cp_async16(s + 2 * TILE_BYTES,      B0 + g);
    cp_async16(s + 2 * TILE_BYTES + 16, B0 + g + 8);
    cp_async16(s + 3 * TILE_BYTES,      B1 + g);
    cp_async16(s + 3 * TILE_BYTES + 16, B1 + g + 8);
}

__device__ __forceinline__ void ldA(uint32_t smA, int wm, int lane, int k0, uint32_t a[4][4]) {
    int lrow = ((lane >> 3) & 1) * 8 + (lane & 7);
    int lcol = (lane >> 4) * 8 + k0;
#pragma unroll
    for (int mt = 0; mt < 4; mt++)
        ldsm_x4(a[mt][0], a[mt][1], a[mt][2], a[mt][3],
                smA + (wm + mt * 16 + lrow) * PITCHB + lcol * 2);
}
__device__ __forceinline__ void ldB(uint32_t smB, int wn, int lane, int k0, uint32_t b[4][2]) {
    int brow = ((lane >> 4) & 1) * 8 + (lane & 7);
    int bcol = ((lane >> 3) & 1) * 8 + k0;
#pragma unroll
    for (int j2 = 0; j2 < 2; j2++) {
        uint32_t r0, r1, r2, r3;
        ldsm_x4(r0, r1, r2, r3, smB + (wn + j2 * 16 + brow) * PITCHB + bcol * 2);
        b[j2 * 2][0] = r0; b[j2 * 2][1] = r1;
        b[j2 * 2 + 1][0] = r2; b[j2 * 2 + 1][1] = r3;
    }
}

__device__ __forceinline__ void gemm_mainloop(const __nv_bfloat16* Ahi, const __nv_bfloat16* Alo,
                                              const __nv_bfloat16* Bhi, const __nv_bfloat16* Blo,
                                              uint32_t smb, int tid, float acc[4][4][4])
{
    const int wid = tid >> 5, lane = tid & 31;
    const int wm = (wid >> 2) * 64, wn = (wid & 3) * 32;
    const int NCH = Kdim / KCc;  // 32

    load_chunk(Ahi, Alo, Bhi, Blo, smb, 0, tid);            cp_commit();
    load_chunk(Ahi, Alo, Bhi, Blo, smb + BUF_BYTES, 1, tid); cp_commit();

    for (int c = 0; c < NCH; ++c) {
        uint32_t buf = smb + (c & 1) * BUF_BYTES;
        cp_wait1();
        __syncthreads();

        uint32_t smA_hi = buf, smA_lo = buf + TILE_BYTES;
        uint32_t smB_hi = buf + 2 * TILE_BYTES, smB_lo = buf + 3 * TILE_BYTES;
#pragma unroll
        for (int ks = 0; ks < 2; ks++) {
            int k0 = ks * 16;
            uint32_t ah[4][4], al[4][4], bb[4][2];
            ldA(smA_hi, wm, lane, k0, ah);
            ldB(smB_hi, wn, lane, k0, bb);
#pragma unroll
            for (int mt = 0; mt < 4; mt++)
#pragma unroll
                for (int nt = 0; nt < 4; nt++) mma16816(acc[mt][nt], ah[mt], bb[nt]);
            ldA(smA_lo, wm, lane, k0, al);
#pragma unroll
            for (int mt = 0; mt < 4; mt++)
#pragma unroll
                for (int nt = 0; nt < 4; nt++) mma16816(acc[mt][nt], al[mt], bb[nt]);
            ldB(smB_lo, wn, lane, k0, bb);
#pragma unroll
            for (int mt = 0; mt < 4; mt++)
#pragma unroll
                for (int nt = 0; nt < 4; nt++) mma16816(acc[mt][nt], ah[mt], bb[nt]);
        }
        __syncthreads();
        if (c + 2 < NCH) load_chunk(Ahi, Alo, Bhi, Blo, buf, c + 2, tid);
        cp_commit();   // commit every iter (possibly empty) to keep wait accounting simple
    }
}

// ---------------------------------------------------------------------------
// QKV GEMM: z=0: Q = x@Wq ; z=1: K = x2@Wk ; z=2: V = x2@Wv
// epilogue scatters fp32 to head-major [b,h,n,d]
// ---------------------------------------------------------------------------
__global__ __launch_bounds__(256) void qkv_mma_kernel()
{
    extern __shared__ char sm[];
    uint32_t smb = smem_u32(sm);
    int tid = threadIdx.x;
    int z = blockIdx.z;
    int n0 = blockIdx.x * BNt;
    int m0 = blockIdx.y * BMt;

    const __nv_bfloat16* Ahi = (z == 0 ? g_Xhi : g_X2hi) + (size_t)m0 * Kdim;
    const __nv_bfloat16* Alo = (z == 0 ? g_Xlo : g_X2lo) + (size_t)m0 * Kdim;
    const __nv_bfloat16* Bhi = g_Wqhi + (size_t)(z * Hh + n0) * Kdim;
    const __nv_bfloat16* Blo = g_Wqlo + (size_t)(z * Hh + n0) * Kdim;

    float acc[4][4][4];
#pragma unroll
    for (int i = 0; i < 4; i++)
#pragma unroll
        for (int j = 0; j < 4; j++)
#pragma unroll
            for (int k = 0; k < 4; k++) acc[i][j][k] = 0.f;

    gemm_mainloop(Ahi, Alo, Bhi, Blo, smb, tid, acc);

    float* dst = (z == 0) ? g_Q : (z == 1) ? g_K : g_V;
    const int wid = tid >> 5, lane = tid & 31;
    const int wm = (wid >> 2) * 64, wn = (wid & 3) * 32;
#pragma unroll
    for (int mt = 0; mt < 4; mt++) {
#pragma unroll
        for (int nt = 0; nt < 4; nt++) {
            int col = n0 + wn + nt * 8 + (lane & 3) * 2;
            int h = col >> 6, d = col & 63;
#pragma unroll
            for (int half = 0; half < 2; half++) {
                int gm = m0 + wm + mt * 16 + (lane >> 2) + half * 8;
                int b = gm / Nn, n = gm % Nn;
                float2 o = make_float2(acc[mt][nt][half * 2], acc[mt][nt][half * 2 + 1]);
                *(float2*)(dst + ((((size_t)b * NH + h) * Nn) + n) * HD + d) = o;
            }
        }
    }
}

// ---------------------------------------------------------------------------
// Output projection GEMM: out = attn @ Wout + bout
// ---------------------------------------------------------------------------
__global__ __launch_bounds__(256) void proj_mma_kernel(const float* __restrict__ bout,
                                                       float* __restrict__ out)
{
    extern __shared__ char sm[];
    uint32_t smb = smem_u32(sm);
    int tid = threadIdx.x;
    int n0 = blockIdx.x * BNt;
    int m0 = blockIdx.y * BMt;

    const __nv_bfloat16* Ahi = g_Ahi + (size_t)m0 * Kdim;
    const __nv_bfloat16* Alo = g_Alo + (size_t)m0 * Kdim;
    const __nv_bfloat16* Bhi = g_Wohi + (size_t)n0 * Kdim;
    const __nv_bfloat16* Blo = g_Wolo + (size_t)n0 * Kdim;

    float acc[4][4][4];
#pragma unroll
    for (int i = 0; i < 4; i++)
#pragma unroll
        for (int j = 0; j < 4; j++)
#pragma unroll
            for (int k = 0; k < 4; k++) acc[i][j][k] = 0.f;

    gemm_mainloop(Ahi, Alo, Bhi, Blo, smb, tid, acc);

    const int wid = tid >> 5, lane = tid & 31;
    const int wm = (wid >> 2) * 64, wn = (wid & 3) * 32;
#pragma unroll
    for (int mt = 0; mt < 4; mt++) {
#pragma unroll
        for (int nt = 0; nt < 4; nt++) {
            int col = n0 + wn + nt * 8 + (lane & 3) * 2;
            float2 bb = *(const float2*)(bout + col);
#pragma unroll
            for (int half = 0; half < 2; half++) {
                int gm = m0 + wm + mt * 16 + (lane >> 2) + half * 8;
                float2 o = make_float2(acc[mt][nt][half * 2] + bb.x,
                                       acc[mt][nt][half * 2 + 1] + bb.y);
                *(float2*)(out + (size_t)gm * 1024 + col) = o;
            }
        }
    }
}

// ---------------------------------------------------------------------------
// Flash attention (fp32 SIMT; epilogue emits bf16 hi/lo for proj GEMM)
// ---------------------------------------------------------------------------
#define ASTRIDE 68
__global__ __launch_bounds__(256) void attn_kernel()
{
    const int bh = blockIdx.y;
    const int q0 = blockIdx.x * 64;

    const float* Q = g_Q + (size_t)bh * Nn * HD;
    const float* K = g_K + (size_t)bh * Nn * HD;
    const float* V = g_V + (size_t)bh * Nn * HD;

    extern __shared__ float smf[];
    float* Qs  = smf;
    float* KsT = Qs  + 64 * ASTRIDE;
    float* Vs  = KsT + 64 * ASTRIDE;
    float* Ps  = Vs  + 64 * ASTRIDE;

    const int tx = threadIdx.x, ty = threadIdx.y;
    const int tid = ty * 16 + tx;

    for (int e = tid; e < 64 * 16; e += 256) {
        int r = e / 16, c4 = (e % 16) * 4;
        *(float4*)(Qs + r * ASTRIDE + c4) = *(const float4*)(Q + (size_t)(q0 + r) * HD + c4);
    }

    float m_i[4], l_i[4], O[4][4];
#pragma unroll
    for (int i = 0; i < 4; i++) {
        m_i[i] = -INFINITY; l_i[i] = 0.f;
#pragma unroll
        for (int j = 0; j < 4; j++) O[i][j] = 0.f;
    }

    for (int t = 0; t < Nn / 64; ++t) {
        __syncthreads();
        for (int e = tid; e < 64 * 16; e += 256) {
            int r = e / 16, c4 = (e % 16) * 4;
            float4 kv = *(const float4*)(K + (size_t)(t * 64 + r) * HD + c4);
            KsT[(c4 + 0) * ASTRIDE + r] = kv.x;
            KsT[(c4 + 1) * ASTRIDE + r] = kv.y;
            KsT[(c4 + 2) * ASTRIDE + r] = kv.z;
            KsT[(c4 + 3) * ASTRIDE + r] = kv.w;
            *(float4*)(Vs + r * ASTRIDE + c4) = *(const float4*)(V + (size_t)(t * 64 + r) * HD + c4);
        }
        __syncthreads();

        float S[4][4];
#pragma unroll
        for (int i = 0; i < 4; i++)
#pragma unroll
            for (int j = 0; j < 4; j++) S[i][j] = 0.f;

#pragma unroll 8
        for (int k = 0; k < 64; k++) {
            float q0f = Qs[(ty * 4 + 0) * ASTRIDE + k];
            float q1f = Qs[(ty * 4 + 1) * ASTRIDE + k];
            float q2f = Qs[(ty * 4 + 2) * ASTRIDE + k];
            float q3f = Qs[(ty * 4 + 3) * ASTRIDE + k];
            float4 kf = *(float4*)(KsT + k * ASTRIDE + tx * 4);
            S[0][0] += q0f * kf.x; S[0][1] += q0f * kf.y; S[0][2] += q0f * kf.z; S[0][3] += q0f * kf.w;
            S[1][0] += q1f * kf.x; S[1][1] += q1f * kf.y; S[1][2] += q1f * kf.z; S[1][3] += q1f * kf.w;
            S[2][0] += q2f * kf.x; S[2][1] += q2f * kf.y; S[2][2] += q2f * kf.z; S[2][3] += q2f * kf.w;
            S[3][0] += q3f * kf.x; S[3][1] += q3f * kf.y; S[3][2] += q3f * kf.z; S[3][3] += q3f * kf.w;
        }

#pragma unroll
        for (int i = 0; i < 4; i++) {
            float s0 = S[i][0] * SCALE, s1 = S[i][1] * SCALE,
                  s2 = S[i][2] * SCALE, s3 = S[i][3] * SCALE;
            float rm = fmaxf(fmaxf(s0, s1), fmaxf(s2, s3));
#pragma unroll
            for (int off = 8; off >= 1; off >>= 1)
                rm = fmaxf(rm, __shfl_xor_sync(0xffffffffu, rm, off));
            float mn = fmaxf(m_i[i], rm);
            float alpha = __expf(m_i[i] - mn);
            m_i[i] = mn;
            float p0 = __expf(s0 - mn), p1 = __expf(s1 - mn),
                  p2 = __expf(s2 - mn), p3 = __expf(s3 - mn);
            float rs = p0 + p1 + p2 + p3;
#pragma unroll
            for (int off = 8; off >= 1; off >>= 1)
                rs += __shfl_xor_sync(0xffffffffu, rs, off);
            l_i[i] = l_i[i] * alpha + rs;
#pragma unroll
            for (int j = 0; j < 4; j++) O[i][j] *= alpha;
            *(float4*)(Ps + (ty * 4 + i) * ASTRIDE + tx * 4) = make_float4(p0, p1, p2, p3);
        }
        __syncthreads();

#pragma unroll 8
        for (int c = 0; c < 64; c++) {
            float p0f = Ps[(ty * 4 + 0) * ASTRIDE + c];
            float p1f = Ps[(ty * 4 + 1) * ASTRIDE + c];
            float p2f = Ps[(ty * 4 + 2) * ASTRIDE + c];
            float p3f = Ps[(ty * 4 + 3) * ASTRIDE + c];
            float4 vf = *(float4*)(Vs + c * ASTRIDE + tx * 4);
            O[0][0] += p0f * vf.x; O[0][1] += p0f * vf.y; O[0][2] += p0f * vf.z; O[0][3] += p0f * vf.w;
            O[1][0] += p1f * vf.x; O[1][1] += p1f * vf.y; O[1][2] += p1f * vf.z; O[1][3] += p1f * vf.w;
            O[2][0] += p2f * vf.x; O[2][1] += p2f * vf.y; O[2][2] += p2f * vf.z; O[2][3] += p2f * vf.w;
            O[3][0] += p3f * vf.x; O[3][1] += p3f * vf.y; O[3][2] += p3f * vf.z; O[3][3] += p3f * vf.w;
        }
    }

    const int b = bh / NH;
    const int h = bh % NH;
#pragma unroll
    for (int i = 0; i < 4; i++) {
        float inv = 1.f / l_i[i];
        size_t row = (size_t)b * Nn + q0 + ty * 4 + i;
        size_t off = row * Hh + h * HD + tx * 4;
        float o0 = O[i][0] * inv, o1 = O[i][1] * inv, o2 = O[i][2] * inv, o3 = O[i][3] * inv;
        __nv_bfloat16 h0 = __float2bfloat16(o0), h1 = __float2bfloat16(o1),
                      h2 = __float2bfloat16(o2), h3 = __float2bfloat16(o3);
        __nv_bfloat16 l0 = __float2bfloat16(o0 - __bfloat162float(h0));
        __nv_bfloat16 l1 = __float2bfloat16(o1 - __bfloat162float(h1));
        __nv_bfloat16 l2 = __float2bfloat16(o2 - __bfloat162float(h2));
        __nv_bfloat16 l3 = __float2bfloat16(o3 - __bfloat162float(h3));
        __nv_bfloat162* H = (__nv_bfloat162*)(g_Ahi + off);
        H[0] = __halves2bfloat162(h0, h1); H[1] = __halves2bfloat162(h2, h3);
        __nv_bfloat162* L = (__nv_bfloat162*)(g_Alo + off);
        L[0] = __halves2bfloat162(l0, l1); L[1] = __halves2bfloat162(l2, l3);
    }
}

// ---------------------------------------------------------------------------
extern "C" void kernel_launch(void* const* d_in, const int* in_sizes, int n_in,
                              void* d_out, int out_size)
{
    const float* x    = (const float*)d_in[0];
    const float* x2   = (const float*)d_in[1];
    const float* Wqkv = (const float*)d_in[2];
    const float* Wout = (const float*)d_in[3];
    const float* bout = (const float*)d_in[4];
    float* out = (float*)d_out;

    // 0) fp32 -> bf16 hi/lo splits (+ weight transposes)
    {
        __nv_bfloat16 *xh, *xl, *x2h, *x2l, *wqh, *wql, *woh, *wol;
        cudaGetSymbolAddress((void**)&xh,  g_Xhi);  cudaGetSymbolAddress((void**)&xl,  g_Xlo);
        cudaGetSymbolAddress((void**)&x2h, g_X2hi); cudaGetSymbolAddress((void**)&x2l, g_X2lo);
        cudaGetSymbolAddress((void**)&wqh, g_Wqhi); cudaGetSymbolAddress((void**)&wql, g_Wqlo);
        cudaGetSymbolAddress((void**)&woh, g_Wohi); cudaGetSymbolAddress((void**)&wol, g_Wolo);

        int n4 = M_TOT * Kdim / 4;
        split_kernel<<<(n4 + 255) / 256, 256>>>(x,  xh,  xl,  n4);
        split_kernel<<<(n4 + 255) / 256, 256>>>(x2, x2h, x2l, n4);
        tsplit_kernel<<<dim3(3 * Hh / 32, Kdim / 32), dim3(32, 8)>>>(Wqkv, wqh, wql, 3 * Hh);
        tsplit_kernel<<<dim3(Hh / 32,     Kdim / 32), dim3(32, 8)>>>(Wout, woh, wol, Hh);
    }

    // 1) QKV projections (HMMA mma.sync)
    cudaFuncSetAttribute(qkv_mma_kernel, cudaFuncAttributeMaxDynamicSharedMemorySize, GEMM_SMEM);
    qkv_mma_kernel<<<dim3(Hh / BNt, M_TOT / BMt, 3), 256, GEMM_SMEM>>>();

    // 2) Flash attention (fp32 SIMT)
    const size_t attn_smem = 4 * 64 * ASTRIDE * sizeof(float);
    cudaFuncSetAttribute(attn_kernel, cudaFuncAttributeMaxDynamicSharedMemorySize, (int)attn_smem);
    attn_kernel<<<dim3(Nn / 64, Bb * NH), dim3(16, 16), attn_smem>>>();

    // 3) Output projection (HMMA mma.sync)
    cudaFuncSetAttribute(proj_mma_kernel, cudaFuncAttributeMaxDynamicSharedMemorySize, GEMM_SMEM);
    proj_mma_kernel<<<dim3(Hh / BNt, M_TOT / BMt), 256, GEMM_SMEM>>>(bout, out);
}

// round 4
// speedup vs baseline: 2.5197x; 1.8858x over previous
#include <cuda_runtime.h>
#include <cuda_bf16.h>
#include <math.h>
#include <stdint.h>

// Problem constants
#define Bb 2
#define Nn 2048
#define Hh 1024
#define NH 16
#define HD 64
#define SCALE 0.125f
#define Kdim 1024
#define M_TOT (Bb*Nn)   // 4096

// ---------------------------------------------------------------------------
// Scratch (device globals; no allocations allowed)
// ---------------------------------------------------------------------------
__device__ __align__(128) __nv_bfloat16 g_Xhi [M_TOT*Kdim];
__device__ __align__(128) __nv_bfloat16 g_Xlo [M_TOT*Kdim];
__device__ __align__(128) __nv_bfloat16 g_X2hi[M_TOT*Kdim];
__device__ __align__(128) __nv_bfloat16 g_X2lo[M_TOT*Kdim];
__device__ __align__(128) __nv_bfloat16 g_Wqhi[3*Hh*Kdim];   // Wqkv^T [3072][1024]
__device__ __align__(128) __nv_bfloat16 g_Wqlo[3*Hh*Kdim];
__device__ __align__(128) __nv_bfloat16 g_Wohi[Hh*Kdim];     // Wout^T [1024][1024]
__device__ __align__(128) __nv_bfloat16 g_Wolo[Hh*Kdim];
// Q/K/V bf16 hi/lo, head-major [b,h,n,d]
__device__ __align__(128) __nv_bfloat16 g_Qhi[Bb*NH*Nn*HD];
__device__ __align__(128) __nv_bfloat16 g_Qlo[Bb*NH*Nn*HD];
__device__ __align__(128) __nv_bfloat16 g_Khi[Bb*NH*Nn*HD];
__device__ __align__(128) __nv_bfloat16 g_Klo[Bb*NH*Nn*HD];
__device__ __align__(128) __nv_bfloat16 g_Vhi[Bb*NH*Nn*HD];
__device__ __align__(128) __nv_bfloat16 g_Vlo[Bb*NH*Nn*HD];
__device__ __align__(128) __nv_bfloat16 g_Ahi[M_TOT*Hh];     // attn out split [b*n][h*d]
__device__ __align__(128) __nv_bfloat16 g_Alo[M_TOT*Hh];

// ---------------------------------------------------------------------------
// PTX helpers (portable: cp.async + ldmatrix + mma.sync — no tcgen05)
// ---------------------------------------------------------------------------
__device__ __forceinline__ uint32_t smem_u32(const void* p) {
    return (uint32_t)__cvta_generic_to_shared(p);
}
__device__ __forceinline__ void cp_async16(uint32_t d, const void* s) {
    asm volatile("cp.async.cg.shared.global [%0], [%1], 16;\n" :: "r"(d), "l"(s) : "memory");
}
__device__ __forceinline__ void cp_commit() { asm volatile("cp.async.commit_group;\n" ::: "memory"); }
__device__ __forceinline__ void cp_wait1()  { asm volatile("cp.async.wait_group 1;\n" ::: "memory"); }
__device__ __forceinline__ void cp_wait2()  { asm volatile("cp.async.wait_group 2;\n" ::: "memory"); }
__device__ __forceinline__ void ldsm_x4(uint32_t& r0, uint32_t& r1, uint32_t& r2, uint32_t& r3, uint32_t a) {
    asm volatile("ldmatrix.sync.aligned.m8n8.x4.shared.b16 {%0,%1,%2,%3}, [%4];"
                 : "=r"(r0), "=r"(r1), "=r"(r2), "=r"(r3) : "r"(a));
}
__device__ __forceinline__ void ldsm_x4_t(uint32_t& r0, uint32_t& r1, uint32_t& r2, uint32_t& r3, uint32_t a) {
    asm volatile("ldmatrix.sync.aligned.m8n8.x4.trans.shared.b16 {%0,%1,%2,%3}, [%4];"
                 : "=r"(r0), "=r"(r1), "=r"(r2), "=r"(r3) : "r"(a));
}
__device__ __forceinline__ void mma16816(float c[4], const uint32_t a[4], const uint32_t b[2]) {
    asm volatile("mma.sync.aligned.m16n8k16.row.col.f32.bf16.bf16.f32 "
                 "{%0,%1,%2,%3}, {%4,%5,%6,%7}, {%8,%9}, {%0,%1,%2,%3};"
                 : "+f"(c[0]), "+f"(c[1]), "+f"(c[2]), "+f"(c[3])
                 : "r"(a[0]), "r"(a[1]), "r"(a[2]), "r"(a[3]), "r"(b[0]), "r"(b[1]));
}
__device__ __forceinline__ float ex2f(float x) {
    float y; asm("ex2.approx.f32 %0, %1;" : "=f"(y) : "f"(x)); return y;
}
__device__ __forceinline__ uint32_t packbf(float lo, float hi) {
    __nv_bfloat162 v = __halves2bfloat162(__float2bfloat16(lo), __float2bfloat16(hi));
    return *(uint32_t*)&v;
}

// ---------------------------------------------------------------------------
// GEMM tiling constants
// ---------------------------------------------------------------------------
#define BMt 128
#define BNt 128
#define KCc 32
#define PITCHB 80                   // bytes per smem row (32 bf16 + 8 pad)
#define TILE_BYTES (128*PITCHB)     // 10240
#define BUF_BYTES (4*TILE_BYTES)    // 40960
#define GEMM_SMEM (2*BUF_BYTES)     // 81920

// ---------------------------------------------------------------------------
// fp32 -> bf16 hi/lo split (element-wise)
// ---------------------------------------------------------------------------
__global__ __launch_bounds__(256) void split_kernel(const float* __restrict__ src,
                                                    __nv_bfloat16* __restrict__ hi,
                                                    __nv_bfloat16* __restrict__ lo,
                                                    int n4)
{
    int i = blockIdx.x * blockDim.x + threadIdx.x;
    if (i >= n4) return;
    float4 v = ((const float4*)src)[i];
    __nv_bfloat16 h0 = __float2bfloat16(v.x), h1 = __float2bfloat16(v.y),
                  h2 = __float2bfloat16(v.z), h3 = __float2bfloat16(v.w);
    __nv_bfloat16 l0 = __float2bfloat16(v.x - __bfloat162float(h0));
    __nv_bfloat16 l1 = __float2bfloat16(v.y - __bfloat162float(h1));
    __nv_bfloat16 l2 = __float2bfloat16(v.z - __bfloat162float(h2));
    __nv_bfloat16 l3 = __float2bfloat16(v.w - __bfloat162float(h3));
    __nv_bfloat162* H = (__nv_bfloat162*)(hi + (size_t)i * 4);
    H[0] = __halves2bfloat162(h0, h1); H[1] = __halves2bfloat162(h2, h3);
    __nv_bfloat162* L = (__nv_bfloat162*)(lo + (size_t)i * 4);
    L[0] = __halves2bfloat162(l0, l1); L[1] = __halves2bfloat162(l2, l3);
}

// Transpose + split: src [1024][C] fp32 -> dst [C][1024] bf16 hi/lo
__global__ __launch_bounds__(256) void tsplit_kernel(const float* __restrict__ src,
                                                     __nv_bfloat16* __restrict__ hi,
                                                     __nv_bfloat16* __restrict__ lo,
                                                     int C)
{
    __shared__ float tile[32][33];
    int c0 = blockIdx.x * 32, k0 = blockIdx.y * 32;
    int tx = threadIdx.x, ty = threadIdx.y;  // 32x8
#pragma unroll
    for (int i = 0; i < 32; i += 8)
        tile[ty + i][tx] = src[(size_t)(k0 + ty + i) * C + c0 + tx];
    __syncthreads();
#pragma unroll
    for (int i = 0; i < 32; i += 8) {
        float v = tile[tx][ty + i];
        __nv_bfloat16 h = __float2bfloat16(v);
        __nv_bfloat16 l = __float2bfloat16(v - __bfloat162float(h));
        size_t o = (size_t)(c0 + ty + i) * 1024 + k0 + tx;
        hi[o] = h; lo[o] = l;
    }
}

// ---------------------------------------------------------------------------
// HMMA GEMM mainloop (as round 3): C[128,128] = (Ahi+Alo)@(Bhi+Blo)^T, K=1024
// ---------------------------------------------------------------------------
__device__ __forceinline__ void load_chunk(const __nv_bfloat16* A0, const __nv_bfloat16* A1,
                                           const __nv_bfloat16* B0, const __nv_bfloat16* B1,
                                           uint32_t smbuf, int c, int tid)
{
    int row  = tid >> 1;
    int half = (tid & 1) * 2;
    size_t g = (size_t)row * Kdim + (size_t)c * KCc + half * 8;
    uint32_t s = smbuf + row * PITCHB + half * 16;
    cp_async16(s,                       A0 + g);
    cp_async16(s + 16,                  A0 + g + 8);
    cp_async16(s + TILE_BYTES,          A1 + g);
    cp_async16(s + TILE_BYTES + 16,     A1 + g + 8);
    cp_async16(s + 2 * TILE_BYTES,      B0 + g);
    cp_async16(s + 2 * TILE_BYTES + 16, B0 + g + 8);
    cp_async16(s + 3 * TILE_BYTES,      B1 + g);
    cp_async16(s + 3 * TILE_BYTES + 16, B1 + g + 8);
}

__device__ __forceinline__ void ldA(uint32_t smA, int wm, int lane, int k0, uint32_t a[4][4]) {
    int lrow = lane & 15;
    int lcol = (lane >> 4) * 8 + k0;
#pragma unroll
    for (int mt = 0; mt < 4; mt++)
        ldsm_x4(a[mt][0], a[mt][1], a[mt][2], a[mt][3],
                smA + (wm + mt * 16 + lrow) * PITCHB + lcol * 2);
}
__device__ __forceinline__ void ldB(uint32_t smB, int wn, int lane, int k0, uint32_t b[4][2]) {
    int brow = ((lane >> 4) & 1) * 8 + (lane & 7);
    int bcol = ((lane >> 3) & 1) * 8 + k0;
#pragma unroll
    for (int j2 = 0; j2 < 2; j2++) {
        uint32_t r0, r1, r2, r3;
        ldsm_x4(r0, r1, r2, r3, smB + (wn + j2 * 16 + brow) * PITCHB + bcol * 2);
        b[j2 * 2][0] = r0; b[j2 * 2][1] = r1;
        b[j2 * 2 + 1][0] = r2; b[j2 * 2 + 1][1] = r3;
    }
}

__device__ __forceinline__ void gemm_mainloop(const __nv_bfloat16* Ahi, const __nv_bfloat16* Alo,
                                              const __nv_bfloat16* Bhi, const __nv_bfloat16* Blo,
                                              uint32_t smb, int tid, float acc[4][4][4])
{
    const int wid = tid >> 5, lane = tid & 31;
    const int wm = (wid >> 2) * 64, wn = (wid & 3) * 32;
    const int NCH = Kdim / KCc;  // 32

    load_chunk(Ahi, Alo, Bhi, Blo, smb, 0, tid);             cp_commit();
    load_chunk(Ahi, Alo, Bhi, Blo, smb + BUF_BYTES, 1, tid); cp_commit();

    for (int c = 0; c < NCH; ++c) {
        uint32_t buf = smb + (c & 1) * BUF_BYTES;
        cp_wait1();
        __syncthreads();

        uint32_t smA_hi = buf, smA_lo = buf + TILE_BYTES;
        uint32_t smB_hi = buf + 2 * TILE_BYTES, smB_lo = buf + 3 * TILE_BYTES;
#pragma unroll
        for (int ks = 0; ks < 2; ks++) {
            int k0 = ks * 16;
            uint32_t ah[4][4], al[4][4], bb[4][2];
            ldA(smA_hi, wm, lane, k0, ah);
            ldB(smB_hi, wn, lane, k0, bb);
#pragma unroll
            for (int mt = 0; mt < 4; mt++)
#pragma unroll
                for (int nt = 0; nt < 4; nt++) mma16816(acc[mt][nt], ah[mt], bb[nt]);
            ldA(smA_lo, wm, lane, k0, al);
#pragma unroll
            for (int mt = 0; mt < 4; mt++)
#pragma unroll
                for (int nt = 0; nt < 4; nt++) mma16816(acc[mt][nt], al[mt], bb[nt]);
            ldB(smB_lo, wn, lane, k0, bb);
#pragma unroll
            for (int mt = 0; mt < 4; mt++)
#pragma unroll
                for (int nt = 0; nt < 4; nt++) mma16816(acc[mt][nt], ah[mt], bb[nt]);
        }
        __syncthreads();
        if (c + 2 < NCH) load_chunk(Ahi, Alo, Bhi, Blo, buf, c + 2, tid);
        cp_commit();
    }
}

// ---------------------------------------------------------------------------
// QKV GEMM: epilogue writes bf16 hi/lo head-major [b,h,n,d]
// ---------------------------------------------------------------------------
__global__ __launch_bounds__(256) void qkv_mma_kernel()
{
    extern __shared__ char sm[];
    uint32_t smb = smem_u32(sm);
    int tid = threadIdx.x;
    int z = blockIdx.z;
    int n0 = blockIdx.x * BNt;
    int m0 = blockIdx.y * BMt;

    const __nv_bfloat16* Ahi = (z == 0 ? g_Xhi : g_X2hi) + (size_t)m0 * Kdim;
    const __nv_bfloat16* Alo = (z == 0 ? g_Xlo : g_X2lo) + (size_t)m0 * Kdim;
    const __nv_bfloat16* Bhi = g_Wqhi + (size_t)(z * Hh + n0) * Kdim;
    const __nv_bfloat16* Blo = g_Wqlo + (size_t)(z * Hh + n0) * Kdim;

    float acc[4][4][4];
#pragma unroll
    for (int i = 0; i < 4; i++)
#pragma unroll
        for (int j = 0; j < 4; j++)
#pragma unroll
            for (int k = 0; k < 4; k++) acc[i][j][k] = 0.f;

    gemm_mainloop(Ahi, Alo, Bhi, Blo, smb, tid, acc);

    __nv_bfloat16* dhi = (z == 0) ? g_Qhi : (z == 1) ? g_Khi : g_Vhi;
    __nv_bfloat16* dlo = (z == 0) ? g_Qlo : (z == 1) ? g_Klo : g_Vlo;
    const int wid = tid >> 5, lane = tid & 31;
    const int wm = (wid >> 2) * 64, wn = (wid & 3) * 32;
#pragma unroll
    for (int mt = 0; mt < 4; mt++) {
#pragma unroll
        for (int nt = 0; nt < 4; nt++) {
            int col = n0 + wn + nt * 8 + (lane & 3) * 2;
            int h = col >> 6, d = col & 63;
#pragma unroll
            for (int half = 0; half < 2; half++) {
                int gm = m0 + wm + mt * 16 + (lane >> 2) + half * 8;
                int b = gm / Nn, n = gm % Nn;
                float v0 = acc[mt][nt][half * 2], v1 = acc[mt][nt][half * 2 + 1];
                float h0 = __bfloat162float(__float2bfloat16(v0));
                float h1 = __bfloat162float(__float2bfloat16(v1));
                size_t idx = ((((size_t)b * NH + h) * Nn) + n) * HD + d;
                *(uint32_t*)(dhi + idx) = packbf(h0, h1);
                *(uint32_t*)(dlo + idx) = packbf(v0 - h0, v1 - h1);
            }
        }
    }
}

// ---------------------------------------------------------------------------
// Output projection GEMM: out = attn @ Wout + bout
// ---------------------------------------------------------------------------
__global__ __launch_bounds__(256) void proj_mma_kernel(const float* __restrict__ bout,
                                                       float* __restrict__ out)
{
    extern __shared__ char sm[];
    uint32_t smb = smem_u32(sm);
    int tid = threadIdx.x;
    int n0 = blockIdx.x * BNt;
    int m0 = blockIdx.y * BMt;

    const __nv_bfloat16* Ahi = g_Ahi + (size_t)m0 * Kdim;
    const __nv_bfloat16* Alo = g_Alo + (size_t)m0 * Kdim;
    const __nv_bfloat16* Bhi = g_Wohi + (size_t)n0 * Kdim;
    const __nv_bfloat16* Blo = g_Wolo + (size_t)n0 * Kdim;

    float acc[4][4][4];
#pragma unroll
    for (int i = 0; i < 4; i++)
#pragma unroll
        for (int j = 0; j < 4; j++)
#pragma unroll
            for (int k = 0; k < 4; k++) acc[i][j][k] = 0.f;

    gemm_mainloop(Ahi, Alo, Bhi, Blo, smb, tid, acc);

    const int wid = tid >> 5, lane = tid & 31;
    const int wm = (wid >> 2) * 64, wn = (wid & 3) * 32;
#pragma unroll
    for (int mt = 0; mt < 4; mt++) {
#pragma unroll
        for (int nt = 0; nt < 4; nt++) {
            int col = n0 + wn + nt * 8 + (lane & 3) * 2;
            float2 bb = *(const float2*)(bout + col);
#pragma unroll
            for (int half = 0; half < 2; half++) {
                int gm = m0 + wm + mt * 16 + (lane >> 2) + half * 8;
                float2 o = make_float2(acc[mt][nt][half * 2] + bb.x,
                                       acc[mt][nt][half * 2 + 1] + bb.y);
                *(float2*)(out + (size_t)gm * 1024 + col) = o;
            }
        }
    }
}

// ---------------------------------------------------------------------------
// Tensor-core flash attention
// CTA: 128 queries of one (b,h). 8 warps x 16 rows. kv tiles of 64.
// smem pitch 144B (72 bf16) -> conflict-free ldmatrix.
// ---------------------------------------------------------------------------
#define APITCHB 144
#define QT 128
#define KVT 64
#define MATB (64*APITCHB)            // 9216 bytes per kv matrix
#define KVBUF (4*MATB)               // Khi|Klo|Vhi|Vlo = 36864
#define QBYTES (128*APITCHB)         // 18432 per Q matrix
#define ATTN_SMEM (2*QBYTES + 2*KVBUF)  // 110592

__device__ __forceinline__ void load_kv_tile(const __nv_bfloat16* const mats[4],
                                             uint32_t bufb, int t, int tid)
{
#pragma unroll
    for (int i = 0; i < 8; i++) {
        int e = tid + i * 256;
        int mat = e >> 9;
        int row = (e >> 3) & 63;
        int c   = e & 7;
        cp_async16(bufb + mat * MATB + row * APITCHB + c * 16,
                   mats[mat] + ((size_t)(t * KVT + row)) * HD + c * 8);
    }
}

__global__ __launch_bounds__(256, 1) void attn_mma_kernel()
{
    extern __shared__ char sm[];
    uint32_t smb = smem_u32(sm);
    const uint32_t QHI = smb, QLO = smb + QBYTES;
    const uint32_t KV0 = smb + 2 * QBYTES;

    const int tid = threadIdx.x, lane = tid & 31, wid = tid >> 5;
    const int bh = blockIdx.y, q0 = blockIdx.x * QT;

    const size_t base = (size_t)bh * Nn * HD;
    const __nv_bfloat16* Qh = g_Qhi + base + (size_t)q0 * HD;
    const __nv_bfloat16* Ql = g_Qlo + base + (size_t)q0 * HD;
    const __nv_bfloat16* kvmats[4] = { g_Khi + base, g_Klo + base, g_Vhi + base, g_Vlo + base };

    // Load Q (hi+lo): 2 mats x 128 rows x 8 chunks = 2048 -> 8/thread
#pragma unroll
    for (int i = 0; i < 8; i++) {
        int e = tid + i * 256;
        int mat = e >> 10;
        int row = (e >> 3) & 127;
        int c   = e & 7;
        const __nv_bfloat16* src = (mat == 0 ? Qh : Ql) + (size_t)row * HD + c * 8;
        cp_async16((mat == 0 ? QHI : QLO) + row * APITCHB + c * 16, src);
    }
    cp_commit();
    load_kv_tile(kvmats, KV0, 0, tid);          cp_commit();
    load_kv_tile(kvmats, KV0 + KVBUF, 1, tid);  cp_commit();

    cp_wait2();         // Q ready
    __syncthreads();

    // Q fragments (once)
    uint32_t aqh[4][4], aql[4][4];
    {
        int lrow = lane & 15;
        int lcolB = (lane >> 4) * 16;
        uint32_t qrow = (wid * 16 + lrow) * APITCHB + lcolB;
#pragma unroll
        for (int kt = 0; kt < 4; kt++) {
            ldsm_x4(aqh[kt][0], aqh[kt][1], aqh[kt][2], aqh[kt][3], QHI + qrow + kt * 32);
            ldsm_x4(aql[kt][0], aql[kt][1], aql[kt][2], aql[kt][3], QLO + qrow + kt * 32);
        }
    }

    float O[8][4];
#pragma unroll
    for (int i = 0; i < 8; i++)
#pragma unroll
        for (int j = 0; j < 4; j++) O[i][j] = 0.f;
    float m0 = -INFINITY, m1 = -INFINITY, l0 = 0.f, l1 = 0.f;
    const float cc = SCALE * 1.4426950408889634f;   // scale * log2(e)

    // fragment address components
    const int brow = ((lane >> 4) & 1) * 8 + (lane & 7);      // K (non-trans)
    const int bcolB = ((lane >> 3) & 1) * 16;
    const int vrow = lane & 15;                                // V (trans)
    const int vcolB = ((lane >> 4) & 1) * 16;

    for (int t = 0; t < Nn / KVT; ++t) {
        uint32_t buf = KV0 + (t & 1) * KVBUF;
        cp_wait1();
        __syncthreads();

        uint32_t KHIb = buf, KLOb = buf + MATB, VHIb = buf + 2 * MATB, VLOb = buf + 3 * MATB;

        // ---- S = Q K^T (3-pass split) ----
        float S[8][4];
#pragma unroll
        for (int i = 0; i < 8; i++)
#pragma unroll
            for (int j = 0; j < 4; j++) S[i][j] = 0.f;

        uint32_t bk[8][2];
#pragma unroll
        for (int kt = 0; kt < 4; kt++) {
            uint32_t colB = kt * 32 + bcolB;
#pragma unroll
            for (int g = 0; g < 4; g++)
                ldsm_x4(bk[2 * g][0], bk[2 * g][1], bk[2 * g + 1][0], bk[2 * g + 1][1],
                        KHIb + (g * 16 + brow) * APITCHB + colB);
#pragma unroll
            for (int nt = 0; nt < 8; nt++) mma16816(S[nt], aqh[kt], bk[nt]);
#pragma unroll
            for (int nt = 0; nt < 8; nt++) mma16816(S[nt], aql[kt], bk[nt]);
#pragma unroll
            for (int g = 0; g < 4; g++)
                ldsm_x4(bk[2 * g][0], bk[2 * g][1], bk[2 * g + 1][0], bk[2 * g + 1][1],
                        KLOb + (g * 16 + brow) * APITCHB + colB);
#pragma unroll
            for (int nt = 0; nt < 8; nt++) mma16816(S[nt], aqh[kt], bk[nt]);
        }

        // ---- online softmax (rows r0 = lane>>2, r1 = r0+8) ----
        float rm0 = -INFINITY, rm1 = -INFINITY;
#pragma unroll
        for (int j = 0; j < 8; j++) {
            rm0 = fmaxf(rm0, fmaxf(S[j][0], S[j][1]));
            rm1 = fmaxf(rm1, fmaxf(S[j][2], S[j][3]));
        }
        rm0 = fmaxf(rm0, __shfl_xor_sync(0xffffffffu, rm0, 1));
        rm0 = fmaxf(rm0, __shfl_xor_sync(0xffffffffu, rm0, 2));
        rm1 = fmaxf(rm1, __shfl_xor_sync(0xffffffffu, rm1, 1));
        rm1 = fmaxf(rm1, __shfl_xor_sync(0xffffffffu, rm1, 2));
        float mn0 = fmaxf(m0, rm0), mn1 = fmaxf(m1, rm1);
        float a0 = ex2f((m0 - mn0) * cc), a1 = ex2f((m1 - mn1) * cc);
        m0 = mn0; m1 = mn1;
        float mc0 = mn0 * cc, mc1 = mn1 * cc;

        uint32_t phi[4][4], plo[4][4];
        float rs0 = 0.f, rs1 = 0.f;
#pragma unroll
        for (int j = 0; j < 8; j++) {
            float p0 = ex2f(fmaf(S[j][0], cc, -mc0));
            float p1 = ex2f(fmaf(S[j][1], cc, -mc0));
            float p2 = ex2f(fmaf(S[j][2], cc, -mc1));
            float p3 = ex2f(fmaf(S[j][3], cc, -mc1));
            rs0 += p0 + p1; rs1 += p2 + p3;
            float h0 = __bfloat162float(__float2bfloat16(p0));
            float h1 = __bfloat162float(__float2bfloat16(p1));
            float h2 = __bfloat162float(__float2bfloat16(p2));
            float h3 = __bfloat162float(__float2bfloat16(p3));
            int kt = j >> 1, hf = (j & 1) * 2;
            phi[kt][hf]     = packbf(h0, h1);
            phi[kt][hf + 1] = packbf(h2, h3);
            plo[kt][hf]     = packbf(p0 - h0, p1 - h1);
            plo[kt][hf + 1] = packbf(p2 - h2, p3 - h3);
        }
        // fix ordering: a-frag = {r0 k0-7, r1 k0-7, r0 k8-15, r1 k8-15}
        // phi[kt] currently = {ntile2kt(r0), ntile2kt(r1), ntile2kt+1(r0), ntile2kt+1(r1)} — correct.
        rs0 += __shfl_xor_sync(0xffffffffu, rs0, 1);
        rs0 += __shfl_xor_sync(0xffffffffu, rs0, 2);
        rs1 += __shfl_xor_sync(0xffffffffu, rs1, 1);
        rs1 += __shfl_xor_sync(0xffffffffu, rs1, 2);
        l0 = l0 * a0 + rs0;
        l1 = l1 * a1 + rs1;
#pragma unroll
        for (int dt = 0; dt < 8; dt++) {
            O[dt][0] *= a0; O[dt][1] *= a0; O[dt][2] *= a1; O[dt][3] *= a1;
        }

        // ---- O += P V (3-pass split) ----
        uint32_t bv[8][2];
#pragma unroll
        for (int kt = 0; kt < 4; kt++) {
            uint32_t rowB = (kt * 16 + vrow) * APITCHB + vcolB;
#pragma unroll
            for (int g2 = 0; g2 < 4; g2++)
                ldsm_x4_t(bv[2 * g2][0], bv[2 * g2][1], bv[2 * g2 + 1][0], bv[2 * g2 + 1][1],
                          VHIb + rowB + g2 * 32);
#pragma unroll
            for (int dt = 0; dt < 8; dt++) mma16816(O[dt], phi[kt], bv[dt]);
#pragma unroll
            for (int dt = 0; dt < 8; dt++) mma16816(O[dt], plo[kt], bv[dt]);
#pragma unroll
            for (int g2 = 0; g2 < 4; g2++)
                ldsm_x4_t(bv[2 * g2][0], bv[2 * g2][1], bv[2 * g2 + 1][0], bv[2 * g2 + 1][1],
                          VLOb + rowB + g2 * 32);
#pragma unroll
            for (int dt = 0; dt < 8; dt++) mma16816(O[dt], phi[kt], bv[dt]);
        }

        __syncthreads();
        if (t + 2 < Nn / KVT) load_kv_tile(kvmats, buf, t + 2, tid);
        cp_commit();
    }

    // ---- epilogue: normalize, write bf16 hi/lo to g_Ahi/g_Alo [b*n][h*64+d] ----
    const int b = bh >> 4, h = bh & 15;
    float il0 = 1.f / l0, il1 = 1.f / l1;
    size_t row0 = (size_t)b * Nn + q0 + wid * 16 + (lane >> 2);
    size_t row1 = row0 + 8;
#pragma unroll
    for (int dt = 0; dt < 8; dt++) {
        int col = h * 64 + dt * 8 + (lane & 3) * 2;
        float v0 = O[dt][0] * il0, v1 = O[dt][1] * il0;
        float v2 = O[dt][2] * il1, v3 = O[dt][3] * il1;
        float h0 = __bfloat162float(__float2bfloat16(v0));
        float h1 = __bfloat162float(__float2bfloat16(v1));
        float h2 = __bfloat162float(__float2bfloat16(v2));
        float h3 = __bfloat162float(__float2bfloat16(v3));
        *(uint32_t*)(g_Ahi + row0 * Hh + col) = packbf(h0, h1);
        *(uint32_t*)(g_Alo + row0 * Hh + col) = packbf(v0 - h0, v1 - h1);
        *(uint32_t*)(g_Ahi + row1 * Hh + col) = packbf(h2, h3);
        *(uint32_t*)(g_Alo + row1 * Hh + col) = packbf(v2 - h2, v3 - h3);
    }
}

// ---------------------------------------------------------------------------
extern "C" void kernel_launch(void* const* d_in, const int* in_sizes, int n_in,
                              void* d_out, int out_size)
{
    const float* x    = (const float*)d_in[0];
    const float* x2   = (const float*)d_in[1];
    const float* Wqkv = (const float*)d_in[2];
    const float* Wout = (const float*)d_in[3];
    const float* bout = (const float*)d_in[4];
    float* out = (float*)d_out;

    // 0) fp32 -> bf16 hi/lo splits (+ weight transposes)
    {
        __nv_bfloat16 *xh, *xl, *x2h, *x2l, *wqh, *wql, *woh, *wol;
        cudaGetSymbolAddress((void**)&xh,  g_Xhi);  cudaGetSymbolAddress((void**)&xl,  g_Xlo);
        cudaGetSymbolAddress((void**)&x2h, g_X2hi); cudaGetSymbolAddress((void**)&x2l, g_X2lo);
        cudaGetSymbolAddress((void**)&wqh, g_Wqhi); cudaGetSymbolAddress((void**)&wql, g_Wqlo);
        cudaGetSymbolAddress((void**)&woh, g_Wohi); cudaGetSymbolAddress((void**)&wol, g_Wolo);

        int n4 = M_TOT * Kdim / 4;
        split_kernel<<<(n4 + 255) / 256, 256>>>(x,  xh,  xl,  n4);
        split_kernel<<<(n4 + 255) / 256, 256>>>(x2, x2h, x2l, n4);
        tsplit_kernel<<<dim3(3 * Hh / 32, Kdim / 32), dim3(32, 8)>>>(Wqkv, wqh, wql, 3 * Hh);
        tsplit_kernel<<<dim3(Hh / 32,     Kdim / 32), dim3(32, 8)>>>(Wout, woh, wol, Hh);
    }

    // 1) QKV projections (HMMA)
    cudaFuncSetAttribute(qkv_mma_kernel, cudaFuncAttributeMaxDynamicSharedMemorySize, GEMM_SMEM);
    qkv_mma_kernel<<<dim3(Hh / BNt, M_TOT / BMt, 3), 256, GEMM_SMEM>>>();

    // 2) Tensor-core flash attention
    cudaFuncSetAttribute(attn_mma_kernel, cudaFuncAttributeMaxDynamicSharedMemorySize, ATTN_SMEM);
    attn_mma_kernel<<<dim3(Nn / QT, Bb * NH), 256, ATTN_SMEM>>>();

    // 3) Output projection (HMMA)
    cudaFuncSetAttribute(proj_mma_kernel, cudaFuncAttributeMaxDynamicSharedMemorySize, GEMM_SMEM);
    proj_mma_kernel<<<dim3(Hh / BNt, M_TOT / BMt), 256, GEMM_SMEM>>>(bout, out);
}

// round 5
// speedup vs baseline: 2.6843x; 1.0653x over previous
#include <cuda_runtime.h>
#include <cuda_bf16.h>
#include <math.h>
#include <stdint.h>

// Problem constants
#define Bb 2
#define Nn 2048
#define Hh 1024
#define NH 16
#define HD 64
#define SCALE 0.125f
#define Kdim 1024
#define M_TOT (Bb*Nn)   // 4096

// ---------------------------------------------------------------------------
// Scratch (device globals; no allocations allowed)
// ---------------------------------------------------------------------------
__device__ __align__(128) __nv_bfloat16 g_Xhi [M_TOT*Kdim];
__device__ __align__(128) __nv_bfloat16 g_Xlo [M_TOT*Kdim];
__device__ __align__(128) __nv_bfloat16 g_X2hi[M_TOT*Kdim];
__device__ __align__(128) __nv_bfloat16 g_X2lo[M_TOT*Kdim];
__device__ __align__(128) __nv_bfloat16 g_Wqhi[3*Hh*Kdim];   // Wqkv^T [3072][1024]
__device__ __align__(128) __nv_bfloat16 g_Wqlo[3*Hh*Kdim];
__device__ __align__(128) __nv_bfloat16 g_Wohi[Hh*Kdim];     // Wout^T [1024][1024]
__device__ __align__(128) __nv_bfloat16 g_Wolo[Hh*Kdim];
// Q/K/V bf16 hi/lo, head-major [b,h,n,d]
__device__ __align__(128) __nv_bfloat16 g_Qhi[Bb*NH*Nn*HD];
__device__ __align__(128) __nv_bfloat16 g_Qlo[Bb*NH*Nn*HD];
__device__ __align__(128) __nv_bfloat16 g_Khi[Bb*NH*Nn*HD];
__device__ __align__(128) __nv_bfloat16 g_Klo[Bb*NH*Nn*HD];
__device__ __align__(128) __nv_bfloat16 g_Vhi[Bb*NH*Nn*HD];
__device__ __align__(128) __nv_bfloat16 g_Vlo[Bb*NH*Nn*HD];
__device__ __align__(128) __nv_bfloat16 g_Ahi[M_TOT*Hh];     // attn out split [b*n][h*d]
__device__ __align__(128) __nv_bfloat16 g_Alo[M_TOT*Hh];

// ---------------------------------------------------------------------------
// PTX helpers (portable: cp.async + ldmatrix + mma.sync — no tcgen05)
// ---------------------------------------------------------------------------
__device__ __forceinline__ uint32_t smem_u32(const void* p) {
    return (uint32_t)__cvta_generic_to_shared(p);
}
__device__ __forceinline__ void cp_async16(uint32_t d, const void* s) {
    asm volatile("cp.async.cg.shared.global [%0], [%1], 16;\n" :: "r"(d), "l"(s) : "memory");
}
__device__ __forceinline__ void cp_commit() { asm volatile("cp.async.commit_group;\n" ::: "memory"); }
__device__ __forceinline__ void cp_wait1()  { asm volatile("cp.async.wait_group 1;\n" ::: "memory"); }
__device__ __forceinline__ void cp_wait2()  { asm volatile("cp.async.wait_group 2;\n" ::: "memory"); }
__device__ __forceinline__ void ldsm_x4(uint32_t& r0, uint32_t& r1, uint32_t& r2, uint32_t& r3, uint32_t a) {
    asm volatile("ldmatrix.sync.aligned.m8n8.x4.shared.b16 {%0,%1,%2,%3}, [%4];"
                 : "=r"(r0), "=r"(r1), "=r"(r2), "=r"(r3) : "r"(a));
}
__device__ __forceinline__ void ldsm_x4_t(uint32_t& r0, uint32_t& r1, uint32_t& r2, uint32_t& r3, uint32_t a) {
    asm volatile("ldmatrix.sync.aligned.m8n8.x4.trans.shared.b16 {%0,%1,%2,%3}, [%4];"
                 : "=r"(r0), "=r"(r1), "=r"(r2), "=r"(r3) : "r"(a));
}
__device__ __forceinline__ void mma16816(float c[4], const uint32_t a[4], const uint32_t b[2]) {
    asm volatile("mma.sync.aligned.m16n8k16.row.col.f32.bf16.bf16.f32 "
                 "{%0,%1,%2,%3}, {%4,%5,%6,%7}, {%8,%9}, {%0,%1,%2,%3};"
                 : "+f"(c[0]), "+f"(c[1]), "+f"(c[2]), "+f"(c[3])
                 : "r"(a[0]), "r"(a[1]), "r"(a[2]), "r"(a[3]), "r"(b[0]), "r"(b[1]));
}
__device__ __forceinline__ float ex2f(float x) {
    float y; asm("ex2.approx.f32 %0, %1;" : "=f"(y) : "f"(x)); return y;
}
__device__ __forceinline__ uint32_t packbf(float lo, float hi) {
    __nv_bfloat162 v = __halves2bfloat162(__float2bfloat16(lo), __float2bfloat16(hi));
    return *(uint32_t*)&v;
}

// ---------------------------------------------------------------------------
// GEMM tiling constants
// ---------------------------------------------------------------------------
#define BMt 128
#define BNt 128
#define KCc 32
#define PITCHB 80                   // bytes per smem row (32 bf16 + 8 pad)
#define TILE_BYTES (128*PITCHB)     // 10240
#define BUF_BYTES (4*TILE_BYTES)    // 40960
#define GEMM_SMEM (3*BUF_BYTES)     // 3-stage pipeline = 122880

// ---------------------------------------------------------------------------
// fp32 -> bf16 hi/lo split (element-wise)
// ---------------------------------------------------------------------------
__global__ __launch_bounds__(256) void split_kernel(const float* __restrict__ src,
                                                    __nv_bfloat16* __restrict__ hi,
                                                    __nv_bfloat16* __restrict__ lo,
                                                    int n4)
{
    int i = blockIdx.x * blockDim.x + threadIdx.x;
    if (i >= n4) return;
    float4 v = ((const float4*)src)[i];
    __nv_bfloat16 h0 = __float2bfloat16(v.x), h1 = __float2bfloat16(v.y),
                  h2 = __float2bfloat16(v.z), h3 = __float2bfloat16(v.w);
    __nv_bfloat16 l0 = __float2bfloat16(v.x - __bfloat162float(h0));
    __nv_bfloat16 l1 = __float2bfloat16(v.y - __bfloat162float(h1));
    __nv_bfloat16 l2 = __float2bfloat16(v.z - __bfloat162float(h2));
    __nv_bfloat16 l3 = __float2bfloat16(v.w - __bfloat162float(h3));
    __nv_bfloat162* H = (__nv_bfloat162*)(hi + (size_t)i * 4);
    H[0] = __halves2bfloat162(h0, h1); H[1] = __halves2bfloat162(h2, h3);
    __nv_bfloat162* L = (__nv_bfloat162*)(lo + (size_t)i * 4);
    L[0] = __halves2bfloat162(l0, l1); L[1] = __halves2bfloat162(l2, l3);
}

// Transpose + split: src [1024][C] fp32 -> dst [C][1024] bf16 hi/lo
__global__ __launch_bounds__(256) void tsplit_kernel(const float* __restrict__ src,
                                                     __nv_bfloat16* __restrict__ hi,
                                                     __nv_bfloat16* __restrict__ lo,
                                                     int C)
{
    __shared__ float tile[32][33];
    int c0 = blockIdx.x * 32, k0 = blockIdx.y * 32;
    int tx = threadIdx.x, ty = threadIdx.y;  // 32x8
#pragma unroll
    for (int i = 0; i < 32; i += 8)
        tile[ty + i][tx] = src[(size_t)(k0 + ty + i) * C + c0 + tx];
    __syncthreads();
#pragma unroll
    for (int i = 0; i < 32; i += 8) {
        float v = tile[tx][ty + i];
        __nv_bfloat16 h = __float2bfloat16(v);
        __nv_bfloat16 l = __float2bfloat16(v - __bfloat162float(h));
        size_t o = (size_t)(c0 + ty + i) * 1024 + k0 + tx;
        hi[o] = h; lo[o] = l;
    }
}

// ---------------------------------------------------------------------------
// HMMA GEMM mainloop: C[128,128] = (Ahi+Alo)@(Bhi+Blo)^T, K=1024
// 3-stage cp.async pipeline, ONE __syncthreads per chunk.
// Safety: chunk c writes stage (c+2)%3 (= stage of chunk c-1). Every warp's
// compute of c-1 precedes its arrival at chunk c's barrier, so after the
// barrier the stage is free.
// ---------------------------------------------------------------------------
__device__ __forceinline__ void load_chunk(const __nv_bfloat16* A0, const __nv_bfloat16* A1,
                                           const __nv_bfloat16* B0, const __nv_bfloat16* B1,
                                           uint32_t smbuf, int c, int tid)
{
    int row  = tid >> 1;
    int half = (tid & 1) * 2;
    size_t g = (size_t)row * Kdim + (size_t)c * KCc + half * 8;
    uint32_t s = smbuf + row * PITCHB + half * 16;
    cp_async16(s,                       A0 + g);
    cp_async16(s + 16,                  A0 + g + 8);
    cp_async16(s + TILE_BYTES,          A1 + g);
    cp_async16(s + TILE_BYTES + 16,     A1 + g + 8);
    cp_async16(s + 2 * TILE_BYTES,      B0 + g);
    cp_async16(s + 2 * TILE_BYTES + 16, B0 + g + 8);
    cp_async16(s + 3 * TILE_BYTES,      B1 + g);
    cp_async16(s + 3 * TILE_BYTES + 16, B1 + g + 8);
}

__device__ __forceinline__ void ldA(uint32_t smA, int wm, int lane, int k0, uint32_t a[4][4]) {
    int lrow = lane & 15;
    int lcol = (lane >> 4) * 8 + k0;
#pragma unroll
    for (int mt = 0; mt < 4; mt++)
        ldsm_x4(a[mt][0], a[mt][1], a[mt][2], a[mt][3],
                smA + (wm + mt * 16 + lrow) * PITCHB + lcol * 2);
}
__device__ __forceinline__ void ldB(uint32_t smB, int wn, int lane, int k0, uint32_t b[4][2]) {
    int brow = ((lane >> 4) & 1) * 8 + (lane & 7);
    int bcol = ((lane >> 3) & 1) * 8 + k0;
#pragma unroll
    for (int j2 = 0; j2 < 2; j2++) {
        uint32_t r0, r1, r2, r3;
        ldsm_x4(r0, r1, r2, r3, smB + (wn + j2 * 16 + brow) * PITCHB + bcol * 2);
        b[j2 * 2][0] = r0; b[j2 * 2][1] = r1;
        b[j2 * 2 + 1][0] = r2; b[j2 * 2 + 1][1] = r3;
    }
}

__device__ __forceinline__ void gemm_mainloop(const __nv_bfloat16* Ahi, const __nv_bfloat16* Alo,
                                              const __nv_bfloat16* Bhi, const __nv_bfloat16* Blo,
                                              uint32_t smb, int tid, float acc[4][4][4])
{
    const int wid = tid >> 5, lane = tid & 31;
    const int wm = (wid >> 2) * 64, wn = (wid & 3) * 32;
    const int NCH = Kdim / KCc;  // 32

    load_chunk(Ahi, Alo, Bhi, Blo, smb,             0, tid); cp_commit();
    load_chunk(Ahi, Alo, Bhi, Blo, smb + BUF_BYTES, 1, tid); cp_commit();

    int stage = 0, wstage = 2;
    for (int c = 0; c < NCH; ++c) {
        uint32_t buf = smb + stage * BUF_BYTES;
        cp_wait1();
        __syncthreads();

        uint32_t smA_hi = buf, smA_lo = buf + TILE_BYTES;
        uint32_t smB_hi = buf + 2 * TILE_BYTES, smB_lo = buf + 3 * TILE_BYTES;
#pragma unroll
        for (int ks = 0; ks < 2; ks++) {
            int k0 = ks * 16;
            uint32_t ah[4][4], al[4][4], bb[4][2];
            ldA(smA_hi, wm, lane, k0, ah);
            ldB(smB_hi, wn, lane, k0, bb);
#pragma unroll
            for (int mt = 0; mt < 4; mt++)
#pragma unroll
                for (int nt = 0; nt < 4; nt++) mma16816(acc[mt][nt], ah[mt], bb[nt]);
            ldA(smA_lo, wm, lane, k0, al);
#pragma unroll
            for (int mt = 0; mt < 4; mt++)
#pragma unroll
                for (int nt = 0; nt < 4; nt++) mma16816(acc[mt][nt], al[mt], bb[nt]);
            ldB(smB_lo, wn, lane, k0, bb);
#pragma unroll
            for (int mt = 0; mt < 4; mt++)
#pragma unroll
                for (int nt = 0; nt < 4; nt++) mma16816(acc[mt][nt], ah[mt], bb[nt]);
        }
        if (c + 2 < NCH)
            load_chunk(Ahi, Alo, Bhi, Blo, smb + wstage * BUF_BYTES, c + 2, tid);
        cp_commit();
        stage = (stage + 1) % 3; wstage = (wstage + 1) % 3;
    }
}

// ---------------------------------------------------------------------------
// QKV GEMM: epilogue writes bf16 hi/lo head-major [b,h,n,d]
// ---------------------------------------------------------------------------
__global__ __launch_bounds__(256) void qkv_mma_kernel()
{
    extern __shared__ char sm[];
    uint32_t smb = smem_u32(sm);
    int tid = threadIdx.x;
    int z = blockIdx.z;
    int n0 = blockIdx.x * BNt;
    int m0 = blockIdx.y * BMt;

    const __nv_bfloat16* Ahi = (z == 0 ? g_Xhi : g_X2hi) + (size_t)m0 * Kdim;
    const __nv_bfloat16* Alo = (z == 0 ? g_Xlo : g_X2lo) + (size_t)m0 * Kdim;
    const __nv_bfloat16* Bhi = g_Wqhi + (size_t)(z * Hh + n0) * Kdim;
    const __nv_bfloat16* Blo = g_Wqlo + (size_t)(z * Hh + n0) * Kdim;

    float acc[4][4][4];
#pragma unroll
    for (int i = 0; i < 4; i++)
#pragma unroll
        for (int j = 0; j < 4; j++)
#pragma unroll
            for (int k = 0; k < 4; k++) acc[i][j][k] = 0.f;

    gemm_mainloop(Ahi, Alo, Bhi, Blo, smb, tid, acc);

    __nv_bfloat16* dhi = (z == 0) ? g_Qhi : (z == 1) ? g_Khi : g_Vhi;
    __nv_bfloat16* dlo = (z == 0) ? g_Qlo : (z == 1) ? g_Klo : g_Vlo;
    const int wid = tid >> 5, lane = tid & 31;
    const int wm = (wid >> 2) * 64, wn = (wid & 3) * 32;
#pragma unroll
    for (int mt = 0; mt < 4; mt++) {
#pragma unroll
        for (int nt = 0; nt < 4; nt++) {
            int col = n0 + wn + nt * 8 + (lane & 3) * 2;
            int h = col >> 6, d = col & 63;
#pragma unroll
            for (int half = 0; half < 2; half++) {
                int gm = m0 + wm + mt * 16 + (lane >> 2) + half * 8;
                int b = gm / Nn, n = gm % Nn;
                float v0 = acc[mt][nt][half * 2], v1 = acc[mt][nt][half * 2 + 1];
                float h0 = __bfloat162float(__float2bfloat16(v0));
                float h1 = __bfloat162float(__float2bfloat16(v1));
                size_t idx = ((((size_t)b * NH + h) * Nn) + n) * HD + d;
                *(uint32_t*)(dhi + idx) = packbf(h0, h1);
                *(uint32_t*)(dlo + idx) = packbf(v0 - h0, v1 - h1);
            }
        }
    }
}

// ---------------------------------------------------------------------------
// Output projection GEMM: out = attn @ Wout + bout
// ---------------------------------------------------------------------------
__global__ __launch_bounds__(256) void proj_mma_kernel(const float* __restrict__ bout,
                                                       float* __restrict__ out)
{
    extern __shared__ char sm[];
    uint32_t smb = smem_u32(sm);
    int tid = threadIdx.x;
    int n0 = blockIdx.x * BNt;
    int m0 = blockIdx.y * BMt;

    const __nv_bfloat16* Ahi = g_Ahi + (size_t)m0 * Kdim;
    const __nv_bfloat16* Alo = g_Alo + (size_t)m0 * Kdim;
    const __nv_bfloat16* Bhi = g_Wohi + (size_t)n0 * Kdim;
    const __nv_bfloat16* Blo = g_Wolo + (size_t)n0 * Kdim;

    float acc[4][4][4];
#pragma unroll
    for (int i = 0; i < 4; i++)
#pragma unroll
        for (int j = 0; j < 4; j++)
#pragma unroll
            for (int k = 0; k < 4; k++) acc[i][j][k] = 0.f;

    gemm_mainloop(Ahi, Alo, Bhi, Blo, smb, tid, acc);

    const int wid = tid >> 5, lane = tid & 31;
    const int wm = (wid >> 2) * 64, wn = (wid & 3) * 32;
#pragma unroll
    for (int mt = 0; mt < 4; mt++) {
#pragma unroll
        for (int nt = 0; nt < 4; nt++) {
            int col = n0 + wn + nt * 8 + (lane & 3) * 2;
            float2 bb = *(const float2*)(bout + col);
#pragma unroll
            for (int half = 0; half < 2; half++) {
                int gm = m0 + wm + mt * 16 + (lane >> 2) + half * 8;
                float2 o = make_float2(acc[mt][nt][half * 2] + bb.x,
                                       acc[mt][nt][half * 2 + 1] + bb.y);
                *(float2*)(out + (size_t)gm * 1024 + col) = o;
            }
        }
    }
}

// ---------------------------------------------------------------------------
// Tensor-core flash attention — 3-stage KV pipeline, one sync per tile
// ---------------------------------------------------------------------------
#define APITCHB 144
#define QT 128
#define KVT 64
#define MATB (64*APITCHB)            // 9216 bytes per kv matrix
#define KVBUF (4*MATB)               // Khi|Klo|Vhi|Vlo = 36864
#define QBYTES (128*APITCHB)         // 18432 per Q matrix
#define ATTN_SMEM (2*QBYTES + 3*KVBUF)  // 147456

__device__ __forceinline__ void load_kv_tile(const __nv_bfloat16* const mats[4],
                                             uint32_t bufb, int t, int tid)
{
#pragma unroll
    for (int i = 0; i < 8; i++) {
        int e = tid + i * 256;
        int mat = e >> 9;
        int row = (e >> 3) & 63;
        int c   = e & 7;
        cp_async16(bufb + mat * MATB + row * APITCHB + c * 16,
                   mats[mat] + ((size_t)(t * KVT + row)) * HD + c * 8);
    }
}

__global__ __launch_bounds__(256, 1) void attn_mma_kernel()
{
    extern __shared__ char sm[];
    uint32_t smb = smem_u32(sm);
    const uint32_t QHI = smb, QLO = smb + QBYTES;
    const uint32_t KV0 = smb + 2 * QBYTES;

    const int tid = threadIdx.x, lane = tid & 31, wid = tid >> 5;
    const int bh = blockIdx.y, q0 = blockIdx.x * QT;

    const size_t base = (size_t)bh * Nn * HD;
    const __nv_bfloat16* Qh = g_Qhi + base + (size_t)q0 * HD;
    const __nv_bfloat16* Ql = g_Qlo + base + (size_t)q0 * HD;
    const __nv_bfloat16* kvmats[4] = { g_Khi + base, g_Klo + base, g_Vhi + base, g_Vlo + base };

    // Load Q (hi+lo)
#pragma unroll
    for (int i = 0; i < 8; i++) {
        int e = tid + i * 256;
        int mat = e >> 10;
        int row = (e >> 3) & 127;
        int c   = e & 7;
        const __nv_bfloat16* src = (mat == 0 ? Qh : Ql) + (size_t)row * HD + c * 8;
        cp_async16((mat == 0 ? QHI : QLO) + row * APITCHB + c * 16, src);
    }
    cp_commit();
    load_kv_tile(kvmats, KV0, 0, tid);          cp_commit();
    load_kv_tile(kvmats, KV0 + KVBUF, 1, tid);  cp_commit();

    cp_wait2();         // Q ready
    __syncthreads();

    // Q fragments (once)
    uint32_t aqh[4][4], aql[4][4];
    {
        int lrow = lane & 15;
        int lcolB = (lane >> 4) * 16;
        uint32_t qrow = (wid * 16 + lrow) * APITCHB + lcolB;
#pragma unroll
        for (int kt = 0; kt < 4; kt++) {
            ldsm_x4(aqh[kt][0], aqh[kt][1], aqh[kt][2], aqh[kt][3], QHI + qrow + kt * 32);
            ldsm_x4(aql[kt][0], aql[kt][1], aql[kt][2], aql[kt][3], QLO + qrow + kt * 32);
        }
    }

    float O[8][4];
#pragma unroll
    for (int i = 0; i < 8; i++)
#pragma unroll
        for (int j = 0; j < 4; j++) O[i][j] = 0.f;
    float m0 = -INFINITY, m1 = -INFINITY, l0 = 0.f, l1 = 0.f;
    const float cc = SCALE * 1.4426950408889634f;   // scale * log2(e)

    const int brow = ((lane >> 4) & 1) * 8 + (lane & 7);      // K (non-trans)
    const int bcolB = ((lane >> 3) & 1) * 16;
    const int vrow = lane & 15;                                // V (trans)
    const int vcolB = ((lane >> 4) & 1) * 16;

    int stage = 0, wstage = 2;
    for (int t = 0; t < Nn / KVT; ++t) {
        uint32_t buf = KV0 + stage * KVBUF;
        cp_wait1();
        __syncthreads();

        uint32_t KHIb = buf, KLOb = buf + MATB, VHIb = buf + 2 * MATB, VLOb = buf + 3 * MATB;

        // ---- S = Q K^T (3-pass split) ----
        float S[8][4];
#pragma unroll
        for (int i = 0; i < 8; i++)
#pragma unroll
            for (int j = 0; j < 4; j++) S[i][j] = 0.f;

        uint32_t bk[8][2];
#pragma unroll
        for (int kt = 0; kt < 4; kt++) {
            uint32_t colB = kt * 32 + bcolB;
#pragma unroll
            for (int g = 0; g < 4; g++)
                ldsm_x4(bk[2 * g][0], bk[2 * g][1], bk[2 * g + 1][0], bk[2 * g + 1][1],
                        KHIb + (g * 16 + brow) * APITCHB + colB);
#pragma unroll
            for (int nt = 0; nt < 8; nt++) mma16816(S[nt], aqh[kt], bk[nt]);
#pragma unroll
            for (int nt = 0; nt < 8; nt++) mma16816(S[nt], aql[kt], bk[nt]);
#pragma unroll
            for (int g = 0; g < 4; g++)
                ldsm_x4(bk[2 * g][0], bk[2 * g][1], bk[2 * g + 1][0], bk[2 * g + 1][1],
                        KLOb + (g * 16 + brow) * APITCHB + colB);
#pragma unroll
            for (int nt = 0; nt < 8; nt++) mma16816(S[nt], aqh[kt], bk[nt]);
        }

        // ---- online softmax (rows r0 = lane>>2, r1 = r0+8) ----
        float rm0 = -INFINITY, rm1 = -INFINITY;
#pragma unroll
        for (int j = 0; j < 8; j++) {
            rm0 = fmaxf(rm0, fmaxf(S[j][0], S[j][1]));
            rm1 = fmaxf(rm1, fmaxf(S[j][2], S[j][3]));
        }
        rm0 = fmaxf(rm0, __shfl_xor_sync(0xffffffffu, rm0, 1));
        rm0 = fmaxf(rm0, __shfl_xor_sync(0xffffffffu, rm0, 2));
        rm1 = fmaxf(rm1, __shfl_xor_sync(0xffffffffu, rm1, 1));
        rm1 = fmaxf(rm1, __shfl_xor_sync(0xffffffffu, rm1, 2));
        float mn0 = fmaxf(m0, rm0), mn1 = fmaxf(m1, rm1);
        float a0 = ex2f((m0 - mn0) * cc), a1 = ex2f((m1 - mn1) * cc);
        m0 = mn0; m1 = mn1;
        float mc0 = mn0 * cc, mc1 = mn1 * cc;

        uint32_t phi[4][4], plo[4][4];
        float rs0 = 0.f, rs1 = 0.f;
#pragma unroll
        for (int j = 0; j < 8; j++) {
            float p0 = ex2f(fmaf(S[j][0], cc, -mc0));
            float p1 = ex2f(fmaf(S[j][1], cc, -mc0));
            float p2 = ex2f(fmaf(S[j][2], cc, -mc1));
            float p3 = ex2f(fmaf(S[j][3], cc, -mc1));
            rs0 += p0 + p1; rs1 += p2 + p3;
            float h0 = __bfloat162float(__float2bfloat16(p0));
            float h1 = __bfloat162float(__float2bfloat16(p1));
            float h2 = __bfloat162float(__float2bfloat16(p2));
            float h3 = __bfloat162float(__float2bfloat16(p3));
            int kt = j >> 1, hf = (j & 1) * 2;
            phi[kt][hf]     = packbf(h0, h1);
            phi[kt][hf + 1] = packbf(h2, h3);
            plo[kt][hf]     = packbf(p0 - h0, p1 - h1);
            plo[kt][hf + 1] = packbf(p2 - h2, p3 - h3);
        }
        rs0 += __shfl_xor_sync(0xffffffffu, rs0, 1);
        rs0 += __shfl_xor_sync(0xffffffffu, rs0, 2);
        rs1 += __shfl_xor_sync(0xffffffffu, rs1, 1);
        rs1 += __shfl_xor_sync(0xffffffffu, rs1, 2);
        l0 = l0 * a0 + rs0;
        l1 = l1 * a1 + rs1;
#pragma unroll
        for (int dt = 0; dt < 8; dt++) {
            O[dt][0] *= a0; O[dt][1] *= a0; O[dt][2] *= a1; O[dt][3] *= a1;
        }

        // ---- O += P V (3-pass split) ----
        uint32_t bv[8][2];
#pragma unroll
        for (int kt = 0; kt < 4; kt++) {
            uint32_t rowB = (kt * 16 + vrow) * APITCHB + vcolB;
#pragma unroll
            for (int g2 = 0; g2 < 4; g2++)
                ldsm_x4_t(bv[2 * g2][0], bv[2 * g2][1], bv[2 * g2 + 1][0], bv[2 * g2 + 1][1],
                          VHIb + rowB + g2 * 32);
#pragma unroll
            for (int dt = 0; dt < 8; dt++) mma16816(O[dt], phi[kt], bv[dt]);
#pragma unroll
            for (int dt = 0; dt < 8; dt++) mma16816(O[dt], plo[kt], bv[dt]);
#pragma unroll
            for (int g2 = 0; g2 < 4; g2++)
                ldsm_x4_t(bv[2 * g2][0], bv[2 * g2][1], bv[2 * g2 + 1][0], bv[2 * g2 + 1][1],
                          VLOb + rowB + g2 * 32);
#pragma unroll
            for (int dt = 0; dt < 8; dt++) mma16816(O[dt], phi[kt], bv[dt]);
        }

        if (t + 2 < Nn / KVT)
            load_kv_tile(kvmats, KV0 + wstage * KVBUF, t + 2, tid);
        cp_commit();
        stage = (stage + 1) % 3; wstage = (wstage + 1) % 3;
    }

    // ---- epilogue: normalize, write bf16 hi/lo to g_Ahi/g_Alo [b*n][h*64+d] ----
    const int b = bh >> 4, h = bh & 15;
    float il0 = 1.f / l0, il1 = 1.f / l1;
    size_t row0 = (size_t)b * Nn + q0 + wid * 16 + (lane >> 2);
    size_t row1 = row0 + 8;
#pragma unroll
    for (int dt = 0; dt < 8; dt++) {
        int col = h * 64 + dt * 8 + (lane & 3) * 2;
        float v0 = O[dt][0] * il0, v1 = O[dt][1] * il0;
        float v2 = O[dt][2] * il1, v3 = O[dt][3] * il1;
        float h0 = __bfloat162float(__float2bfloat16(v0));
        float h1 = __bfloat162float(__float2bfloat16(v1));
        float h2 = __bfloat162float(__float2bfloat16(v2));
        float h3 = __bfloat162float(__float2bfloat16(v3));
        *(uint32_t*)(g_Ahi + row0 * Hh + col) = packbf(h0, h1);
        *(uint32_t*)(g_Alo + row0 * Hh + col) = packbf(v0 - h0, v1 - h1);
        *(uint32_t*)(g_Ahi + row1 * Hh + col) = packbf(h2, h3);
        *(uint32_t*)(g_Alo + row1 * Hh + col) = packbf(v2 - h2, v3 - h3);
    }
}

// ---------------------------------------------------------------------------
extern "C" void kernel_launch(void* const* d_in, const int* in_sizes, int n_in,
                              void* d_out, int out_size)
{
    const float* x    = (const float*)d_in[0];
    const float* x2   = (const float*)d_in[1];
    const float* Wqkv = (const float*)d_in[2];
    const float* Wout = (const float*)d_in[3];
    const float* bout = (const float*)d_in[4];
    float* out = (float*)d_out;

    // 0) fp32 -> bf16 hi/lo splits (+ weight transposes)
    {
        __nv_bfloat16 *xh, *xl, *x2h, *x2l, *wqh, *wql, *woh, *wol;
        cudaGetSymbolAddress((void**)&xh,  g_Xhi);  cudaGetSymbolAddress((void**)&xl,  g_Xlo);
        cudaGetSymbolAddress((void**)&x2h, g_X2hi); cudaGetSymbolAddress((void**)&x2l, g_X2lo);
        cudaGetSymbolAddress((void**)&wqh, g_Wqhi); cudaGetSymbolAddress((void**)&wql, g_Wqlo);
        cudaGetSymbolAddress((void**)&woh, g_Wohi); cudaGetSymbolAddress((void**)&wol, g_Wolo);

        int n4 = M_TOT * Kdim / 4;
        split_kernel<<<(n4 + 255) / 256, 256>>>(x,  xh,  xl,  n4);
        split_kernel<<<(n4 + 255) / 256, 256>>>(x2, x2h, x2l, n4);
        tsplit_kernel<<<dim3(3 * Hh / 32, Kdim / 32), dim3(32, 8)>>>(Wqkv, wqh, wql, 3 * Hh);
        tsplit_kernel<<<dim3(Hh / 32,     Kdim / 32), dim3(32, 8)>>>(Wout, woh, wol, Hh);
    }

    // 1) QKV projections (HMMA)
    cudaFuncSetAttribute(qkv_mma_kernel, cudaFuncAttributeMaxDynamicSharedMemorySize, GEMM_SMEM);
    qkv_mma_kernel<<<dim3(Hh / BNt, M_TOT / BMt, 3), 256, GEMM_SMEM>>>();

    // 2) Tensor-core flash attention
    cudaFuncSetAttribute(attn_mma_kernel, cudaFuncAttributeMaxDynamicSharedMemorySize, ATTN_SMEM);
    attn_mma_kernel<<<dim3(Nn / QT, Bb * NH), 256, ATTN_SMEM>>>();

    // 3) Output projection (HMMA)
    cudaFuncSetAttribute(proj_mma_kernel, cudaFuncAttributeMaxDynamicSharedMemorySize, GEMM_SMEM);
    proj_mma_kernel<<<dim3(Hh / BNt, M_TOT / BMt), 256, GEMM_SMEM>>>(bout, out);
}